// round 9
// baseline (speedup 1.0000x reference)
#include <cuda_runtime.h>
#include <cuda_bf16.h>
#include <cstdint>

#define GRP 16
#define BSZ 8192
#define CH  256

// ---------------- scratch (device globals; no allocation allowed) ----------
__device__ float g_G[GRP * CH * CH];            // G = V^T V (upper blocks)
__device__ float g_Tinv[GRP * 8 * 32 * 32];     // diag-block inverses of R
__device__ __nv_bfloat16 g_Vhi[GRP * CH * CH];  // W split
__device__ __nv_bfloat16 g_Vlo[GRP * CH * CH];
__device__ __nv_bfloat16 g_Yhi[GRP * CH * CH];  // Y split
__device__ __nv_bfloat16 g_Ylo[GRP * CH * CH];
__device__ __nv_bfloat16 g_Qhi[GRP * CH * CH];  // Q split (row-major)
__device__ __nv_bfloat16 g_Qlo[GRP * CH * CH];

__device__ __forceinline__ uint32_t smem_u32(const void* p) {
    uint32_t a;
    asm("{ .reg .u64 t; cvta.to.shared.u64 t, %1; cvt.u32.u64 %0, t; }"
        : "=r"(a) : "l"(p));
    return a;
}

#define LDSM4(r, addr)                                                      \
    asm volatile("ldmatrix.sync.aligned.m8n8.x4.shared.b16 {%0,%1,%2,%3}, [%4];" \
                 : "=r"((r)[0]), "=r"((r)[1]), "=r"((r)[2]), "=r"((r)[3])   \
                 : "r"(addr))
#define LDSM4T(r, addr)                                                     \
    asm volatile("ldmatrix.sync.aligned.m8n8.x4.trans.shared.b16 {%0,%1,%2,%3}, [%4];" \
                 : "=r"((r)[0]), "=r"((r)[1]), "=r"((r)[2]), "=r"((r)[3])   \
                 : "r"(addr))
#define MMA(c, a, b0, b1)                                                   \
    asm volatile("mma.sync.aligned.m16n8k16.row.col.f32.bf16.bf16.f32 "     \
                 "{%0,%1,%2,%3}, {%4,%5,%6,%7}, {%8,%9}, {%0,%1,%2,%3};"    \
                 : "+f"((c)[0]), "+f"((c)[1]), "+f"((c)[2]), "+f"((c)[3])   \
                 : "r"((a)[0]), "r"((a)[1]), "r"((a)[2]), "r"((a)[3]),      \
                   "r"(b0), "r"(b1))
#define CP16(dst, src)                                                      \
    asm volatile("cp.async.cg.shared.global [%0], [%1], 16;"                \
                 :: "r"(dst), "l"(src) : "memory")

__device__ __forceinline__ uint32_t pack_hi(float a, float b) {
    __nv_bfloat16 x = __float2bfloat16(a), y = __float2bfloat16(b);
    return ((uint32_t)__bfloat16_as_ushort(y) << 16) | __bfloat16_as_ushort(x);
}
__device__ __forceinline__ uint32_t pack_lo(float a, float b) {
    __nv_bfloat16 x = __float2bfloat16(a), y = __float2bfloat16(b);
    __nv_bfloat16 lx = __float2bfloat16(a - __bfloat162float(x));
    __nv_bfloat16 ly = __float2bfloat16(b - __bfloat162float(y));
    return ((uint32_t)__bfloat16_as_ushort(ly) << 16) | __bfloat16_as_ushort(lx);
}

// ---------------- vsplit: W -> bf16 hi/lo ----------------------------------
__global__ void vsplit(const float* __restrict__ W) {
    int idx = (blockIdx.x * 256 + threadIdx.x) * 4;
    float4 v = *(const float4*)(W + idx);
    uint2 h, l;
    h.x = pack_hi(v.x, v.y); h.y = pack_hi(v.z, v.w);
    l.x = pack_lo(v.x, v.y); l.y = pack_lo(v.z, v.w);
    *(uint2*)&g_Vhi[idx] = h;
    *(uint2*)&g_Vlo[idx] = l;
}

// ---------------- g_mma: G = V^T V (upper 128x128 tiles, HMMA) -------------
#define GSTRIDE 32768u
__global__ void __launch_bounds__(256) g_mma() {
    extern __shared__ __align__(1024) char sm[];
    const uint32_t sb = smem_u32(sm);
    int t = threadIdx.x, warp = t >> 5, lane = t & 31;
    int wm = warp >> 2, wn = warp & 3;
    int g = blockIdx.y;
    int bx = blockIdx.x;                 // 0:(0,0) 1:(0,128) 2:(128,128)
    int a0 = (bx == 2) ? 128 : 0;
    int b0 = (bx == 0) ? 0 : 128;

    const __nv_bfloat16* Vh = g_Vhi + (size_t)g * CH * CH;
    const __nv_bfloat16* Vl = g_Vlo + (size_t)g * CH * CH;

    int kk = t >> 3, g0 = t & 7;
    auto stage = [&](int chk) {
        uint32_t d = sb + (uint32_t)(chk & 1) * GSTRIDE;
        int krow = chk * 32 + kk;
        #pragma unroll
        for (int gi = 0; gi < 2; ++gi) {
            int gr = g0 + gi * 8;
            uint32_t off = (uint32_t)kk * 256 + (uint32_t)((gr ^ (kk & 7)) << 4);
            CP16(d + off,          Vh + (size_t)krow * CH + a0 + gr * 8);
            CP16(d + 8192  + off,  Vl + (size_t)krow * CH + a0 + gr * 8);
            CP16(d + 16384 + off,  Vh + (size_t)krow * CH + b0 + gr * 8);
            CP16(d + 24576 + off,  Vl + (size_t)krow * CH + b0 + gr * 8);
        }
        asm volatile("cp.async.commit_group;" ::: "memory");
    };

    float acc[4][4][4] = {};
    stage(0);
    for (int ch = 0; ch < 8; ++ch) {
        asm volatile("cp.async.wait_group 0;" ::: "memory");
        __syncthreads();
        if (ch < 7) stage(ch + 1);
        uint32_t buf = sb + (uint32_t)(ch & 1) * GSTRIDE;
        #pragma unroll
        for (int ks = 0; ks < 32; ks += 16) {
            uint32_t ah[4][4], al[4][4];
            #pragma unroll
            for (int i = 0; i < 4; ++i) {
                uint32_t mb = (uint32_t)(wm * 64 + i * 16);
                uint32_t krow = (uint32_t)(ks + (lane & 7) + ((lane >> 4) << 3));
                uint32_t gran = (mb >> 3) + ((lane >> 3) & 1);
                uint32_t addr = buf + krow * 256u + ((gran ^ (krow & 7)) << 4);
                LDSM4T(ah[i], addr);
                LDSM4T(al[i], addr + 8192);
            }
            #pragma unroll
            for (int p = 0; p < 2; ++p) {
                uint32_t bh[4], bl[4];
                uint32_t krow = (uint32_t)(ks + (lane & 15));
                uint32_t gran = (uint32_t)(wn * 4 + p * 2 + (lane >> 4));
                uint32_t addr = buf + 16384 + krow * 256u + ((gran ^ (krow & 7)) << 4);
                LDSM4T(bh, addr);
                LDSM4T(bl, addr + 8192);
                #pragma unroll
                for (int i = 0; i < 4; ++i) {
                    MMA(acc[i][2 * p],     ah[i], bh[0], bh[1]);
                    MMA(acc[i][2 * p],     ah[i], bl[0], bl[1]);
                    MMA(acc[i][2 * p],     al[i], bh[0], bh[1]);
                    MMA(acc[i][2 * p + 1], ah[i], bh[2], bh[3]);
                    MMA(acc[i][2 * p + 1], ah[i], bl[2], bl[3]);
                    MMA(acc[i][2 * p + 1], al[i], bh[2], bh[3]);
                }
            }
        }
    }
    float* Gg = g_G + (size_t)g * CH * CH;
    #pragma unroll
    for (int i = 0; i < 4; ++i) {
        int row = a0 + wm * 64 + i * 16 + (lane >> 2);
        #pragma unroll
        for (int j = 0; j < 4; ++j) {
            int col = b0 + wn * 32 + j * 8 + (lane & 3) * 2;
            *(float2*)&Gg[(size_t)row * CH + col]       = make_float2(acc[i][j][0], acc[i][j][1]);
            *(float2*)&Gg[(size_t)(row + 8) * CH + col] = make_float2(acc[i][j][2], acc[i][j][3]);
        }
    }
}

// ---------------- tinv: invert 32x32 diagonal blocks of R ------------------
// R_d = diag(1/beta) + triu(Gd,1). One CTA per group; thread = (block, col).
__global__ void __launch_bounds__(256) tinv_kernel() {
    int g = blockIdx.x;
    int t = threadIdx.x;
    int kb = t >> 5, j = t & 31;

    __shared__ float Ts[8][32][33];
    __shared__ float bet[CH];

    const float* Gg = g_G + (size_t)g * CH * CH;
    bet[t] = 2.0f / Gg[(size_t)t * CH + t];
    __syncthreads();

    int c0 = kb * 32;
    // zero lower part of own column, set diagonal
    for (int i = j + 1; i < 32; ++i) Ts[kb][i][j] = 0.f;
    Ts[kb][j][j] = bet[c0 + j];
    // back substitution up the column
    for (int i = j - 1; i >= 0; --i) {
        float s = 0.f;
        for (int k = i + 1; k <= j; ++k)
            s += Gg[(size_t)(c0 + i) * CH + c0 + k] * Ts[kb][k][j];
        Ts[kb][i][j] = -bet[c0 + i] * s;
    }
    // write own column
    float* Tg = g_Tinv + ((size_t)g * 8 + kb) * 32 * 32;
    for (int i = 0; i < 32; ++i)
        Tg[i * 32 + j] = Ts[kb][i][j];
}

// ---------------- Y = V R^{-1} (block back-substitution, T_d applied) ------
__global__ void y_kernel(const float* __restrict__ W) {
    int g  = blockIdx.y;
    int r0 = blockIdx.x * 32;

    __shared__ float Ys[32][261];
    __shared__ float Gs[32][36];
    __shared__ float Td[32][36];
    __shared__ float pre[32][33];

    const float* Vg = W   + g * CH * CH;
    const float* Gg = g_G + g * CH * CH;

    int t = threadIdx.x;            // 256 threads
    int r = t >> 3, q = t & 7;

    for (int kb = 0; kb < 8; ++kb) {
        int c0 = kb * 32;
        float4 v4 = *(const float4*)&Vg[(r0 + r) * CH + c0 + 4 * q];
        float acc[4] = {v4.x, v4.y, v4.z, v4.w};

        for (int jc = 0; jc < kb; ++jc) {
            int j0 = jc * 32;
            __syncthreads();
            for (int e = t; e < 32 * 32; e += 256) {
                int jj = e >> 5, c = e & 31;
                Gs[jj][c] = Gg[(j0 + jj) * CH + c0 + c];
            }
            __syncthreads();
            #pragma unroll
            for (int jj = 0; jj < 32; ++jj) {
                float yv = Ys[r][j0 + jj];
                float4 gg = *(const float4*)&Gs[jj][4 * q];
                acc[0] -= yv * gg.x;
                acc[1] -= yv * gg.y;
                acc[2] -= yv * gg.z;
                acc[3] -= yv * gg.w;
            }
        }
        pre[r][4 * q + 0] = acc[0];
        pre[r][4 * q + 1] = acc[1];
        pre[r][4 * q + 2] = acc[2];
        pre[r][4 * q + 3] = acc[3];
        // load T_d block
        {
            const float* Tg = g_Tinv + ((size_t)g * 8 + kb) * 32 * 32;
            for (int e = t; e < 32 * 32; e += 256) {
                int ii = e >> 5, c = e & 31;
                Td[ii][c] = Tg[ii * 32 + c];
            }
        }
        __syncthreads();
        // Y block = pre @ T_d  (fully parallel)
        {
            float o0 = 0.f, o1 = 0.f, o2 = 0.f, o3 = 0.f;
            #pragma unroll
            for (int i = 0; i < 32; ++i) {
                float pv = pre[r][i];
                float4 tv = *(const float4*)&Td[i][4 * q];
                o0 += pv * tv.x;
                o1 += pv * tv.y;
                o2 += pv * tv.z;
                o3 += pv * tv.w;
            }
            Ys[r][c0 + 4 * q + 0] = o0;
            Ys[r][c0 + 4 * q + 1] = o1;
            Ys[r][c0 + 4 * q + 2] = o2;
            Ys[r][c0 + 4 * q + 3] = o3;
        }
        __syncthreads();
    }
    for (int e = t; e < 32 * (CH / 2); e += 256) {
        int rr = e >> 7, cc = (e & 127) * 2;
        float v0 = Ys[rr][cc], v1 = Ys[rr][cc + 1];
        size_t idx = ((size_t)g * CH + r0 + rr) * CH + cc;
        *(uint32_t*)&g_Yhi[idx] = pack_hi(v0, v1);
        *(uint32_t*)&g_Ylo[idx] = pack_lo(v0, v1);
    }
}

// ---------------- q_mma: Q = I - Y V^T (128x128 tiles, HMMA) ---------------
#define QSTRIDE 32768u
__global__ void __launch_bounds__(256) q_mma() {
    extern __shared__ __align__(1024) char sm[];
    const uint32_t sb = smem_u32(sm);
    int t = threadIdx.x, warp = t >> 5, lane = t & 31;
    int wm = warp >> 2, wn = warp & 3;
    int g = blockIdx.y;
    int a0 = (blockIdx.x >> 1) * 128, b0 = (blockIdx.x & 1) * 128;

    const __nv_bfloat16* Yh = g_Yhi + (size_t)g * CH * CH;
    const __nv_bfloat16* Yl = g_Ylo + (size_t)g * CH * CH;
    const __nv_bfloat16* Vh = g_Vhi + (size_t)g * CH * CH;
    const __nv_bfloat16* Vl = g_Vlo + (size_t)g * CH * CH;

    int row = t >> 1, gp = (t & 1) * 2;
    auto stage = [&](int chk) {
        uint32_t d = sb + (uint32_t)(chk & 1) * QSTRIDE;
        int k0 = chk * 32;
        #pragma unroll
        for (int gi = 0; gi < 2; ++gi) {
            int gr = gp + gi;
            uint32_t off = (uint32_t)row * 64 + (uint32_t)((gr ^ ((row >> 1) & 3)) << 4);
            CP16(d + off,          Yh + (size_t)(a0 + row) * CH + k0 + gr * 8);
            CP16(d + 8192  + off,  Yl + (size_t)(a0 + row) * CH + k0 + gr * 8);
            CP16(d + 16384 + off,  Vh + (size_t)(b0 + row) * CH + k0 + gr * 8);
            CP16(d + 24576 + off,  Vl + (size_t)(b0 + row) * CH + k0 + gr * 8);
        }
        asm volatile("cp.async.commit_group;" ::: "memory");
    };

    float acc[4][4][4] = {};
    stage(0);
    for (int ch = 0; ch < 8; ++ch) {
        asm volatile("cp.async.wait_group 0;" ::: "memory");
        __syncthreads();
        if (ch < 7) stage(ch + 1);
        uint32_t buf = sb + (uint32_t)(ch & 1) * QSTRIDE;
        #pragma unroll
        for (int ks = 0; ks < 32; ks += 16) {
            uint32_t ah[4][4], al[4][4];
            #pragma unroll
            for (int i = 0; i < 4; ++i) {
                uint32_t mrow = (uint32_t)(wm * 64 + i * 16 + (lane & 15));
                uint32_t gran = (uint32_t)((ks >> 3) + (lane >> 4));
                uint32_t addr = buf + mrow * 64u + ((gran ^ ((mrow >> 1) & 3)) << 4);
                LDSM4(ah[i], addr);
                LDSM4(al[i], addr + 8192);
            }
            #pragma unroll
            for (int p = 0; p < 2; ++p) {
                uint32_t bh[4], bl[4];
                uint32_t nrow = (uint32_t)(wn * 32 + p * 16 + (lane & 7) + ((lane >> 4) << 3));
                uint32_t gran = (uint32_t)((ks >> 3) + ((lane >> 3) & 1));
                uint32_t addr = buf + 16384 + nrow * 64u + ((gran ^ ((nrow >> 1) & 3)) << 4);
                LDSM4(bh, addr);
                LDSM4(bl, addr + 8192);
                #pragma unroll
                for (int i = 0; i < 4; ++i) {
                    MMA(acc[i][2 * p],     ah[i], bh[0], bh[1]);
                    MMA(acc[i][2 * p],     ah[i], bl[0], bl[1]);
                    MMA(acc[i][2 * p],     al[i], bh[0], bh[1]);
                    MMA(acc[i][2 * p + 1], ah[i], bh[2], bh[3]);
                    MMA(acc[i][2 * p + 1], ah[i], bl[2], bl[3]);
                    MMA(acc[i][2 * p + 1], al[i], bh[2], bh[3]);
                }
            }
        }
    }
    #pragma unroll
    for (int i = 0; i < 4; ++i) {
        int rr = a0 + wm * 64 + i * 16 + (lane >> 2);
        #pragma unroll
        for (int j = 0; j < 4; ++j) {
            int cc = b0 + wn * 32 + j * 8 + (lane & 3) * 2;
            float v0 = (rr == cc     ? 1.f : 0.f) - acc[i][j][0];
            float v1 = (rr == cc + 1 ? 1.f : 0.f) - acc[i][j][1];
            float v2 = (rr + 8 == cc     ? 1.f : 0.f) - acc[i][j][2];
            float v3 = (rr + 8 == cc + 1 ? 1.f : 0.f) - acc[i][j][3];
            size_t i0 = ((size_t)g * CH + rr) * CH + cc;
            size_t i1 = ((size_t)g * CH + rr + 8) * CH + cc;
            *(uint32_t*)&g_Qhi[i0] = pack_hi(v0, v1);
            *(uint32_t*)&g_Qlo[i0] = pack_lo(v0, v1);
            *(uint32_t*)&g_Qhi[i1] = pack_hi(v2, v3);
            *(uint32_t*)&g_Qlo[i1] = pack_lo(v2, v3);
        }
    }
}

// ---------------- out = x @ Q via mma.sync bf16 hi/lo split ----------------
// BM=128 BN=256 BK=32; 512 threads, 16 warps as 2m x 8n, warp tile 64x32.
// A: 2 reg-prefetched chunks + 2 smem buffers. B: 4 smem buffers, issue-ahead-2.
#define BM 128
#define BN 256
#define BK 32
#define ABUF 20480u          // per A buffer: hi 10240 + lo 10240
#define BBASE 40960u
#define BBUF 32768u          // per B buffer: hi 16384 + lo 16384
#define SMEM_TOTAL (BBASE + 4u * BBUF)   // 172032

__global__ void __launch_bounds__(512, 1) main_mma(const float* __restrict__ X,
                                                   float* __restrict__ out) {
    extern __shared__ __align__(1024) char sm[];
    const uint32_t sbase = smem_u32(sm);

    int t = threadIdx.x;
    int warp = t >> 5, lane = t & 31;
    int wm = warp >> 3, wn = warp & 7;      // warp tile 64m x 32n
    int g = blockIdx.y;
    int m0 = blockIdx.x * BM;

    const float* Xg = X + ((size_t)g * BSZ + m0) * CH;
    const __nv_bfloat16* Qh = g_Qhi + (size_t)g * CH * CH;
    const __nv_bfloat16* Ql = g_Qlo + (size_t)g * CH * CH;

    int ar = t >> 2, ac = (t & 3) * 8;
    int brow = t >> 4, bg0 = t & 15;

    float acc[4][4][4] = {};
    float4 xa[2][2];

    auto loadA = [&](int ch) {
        xa[ch & 1][0] = *(const float4*)(Xg + (size_t)ar * CH + ch * BK + ac);
        xa[ch & 1][1] = *(const float4*)(Xg + (size_t)ar * CH + ch * BK + ac + 4);
    };
    auto issueB = [&](int ch) {
        uint32_t d = sbase + BBASE + (uint32_t)(ch & 3) * BBUF;
        #pragma unroll
        for (int gi = 0; gi < 2; ++gi) {
            int gr = bg0 + gi * 16;
            uint32_t off = (uint32_t)brow * 512 + (uint32_t)((gr ^ (brow & 7)) << 4);
            const __nv_bfloat16* sh = Qh + (size_t)(ch * BK + brow) * CH + gr * 8;
            const __nv_bfloat16* sl = Ql + (size_t)(ch * BK + brow) * CH + gr * 8;
            CP16(d + off,         sh);
            CP16(d + 16384 + off, sl);
        }
        asm volatile("cp.async.commit_group;" ::: "memory");
    };
    auto storeA = [&](int ch) {
        char* p = sm + (ch & 1) * ABUF;
        float4* x0 = &xa[ch & 1][0];
        float f[8] = {x0[0].x, x0[0].y, x0[0].z, x0[0].w,
                      x0[1].x, x0[1].y, x0[1].z, x0[1].w};
        uint32_t h[4], l[4];
        #pragma unroll
        for (int i = 0; i < 4; ++i) {
            h[i] = pack_hi(f[2 * i], f[2 * i + 1]);
            l[i] = pack_lo(f[2 * i], f[2 * i + 1]);
        }
        uint32_t ao = ar * 80u + ac * 2u;
        *(uint4*)(p + ao)         = make_uint4(h[0], h[1], h[2], h[3]);
        *(uint4*)(p + 10240 + ao) = make_uint4(l[0], l[1], l[2], l[3]);
    };
    auto compute = [&](int ch) {
        uint32_t abuf = sbase + (uint32_t)(ch & 1) * ABUF;
        uint32_t bbuf = sbase + BBASE + (uint32_t)(ch & 3) * BBUF;
        #pragma unroll
        for (int ks = 0; ks < BK; ks += 16) {
            uint32_t ah[4][4], al[4][4];
            #pragma unroll
            for (int i = 0; i < 4; ++i) {
                uint32_t mrow = (uint32_t)(wm * 64 + i * 16 + (lane & 15));
                uint32_t kcol = (uint32_t)(ks + (lane >> 4) * 8);
                uint32_t addr = abuf + mrow * 80u + kcol * 2u;
                LDSM4(ah[i], addr);
                LDSM4(al[i], addr + 10240);
            }
            #pragma unroll
            for (int p = 0; p < 2; ++p) {
                uint32_t bh[4], bl[4];
                uint32_t krow = (uint32_t)(ks + (lane & 15));
                uint32_t gran = (uint32_t)(wn * 4 + p * 2 + (lane >> 4));
                uint32_t addr = bbuf + krow * 512u + ((gran ^ (krow & 7)) << 4);
                LDSM4T(bh, addr);
                LDSM4T(bl, addr + 16384);
                #pragma unroll
                for (int i = 0; i < 4; ++i) {
                    MMA(acc[i][2 * p],     ah[i], bh[0], bh[1]);
                    MMA(acc[i][2 * p],     ah[i], bl[0], bl[1]);
                    MMA(acc[i][2 * p],     al[i], bh[0], bh[1]);
                    MMA(acc[i][2 * p + 1], ah[i], bh[2], bh[3]);
                    MMA(acc[i][2 * p + 1], ah[i], bl[2], bl[3]);
                    MMA(acc[i][2 * p + 1], al[i], bh[2], bh[3]);
                }
            }
        }
    };

    loadA(0); loadA(1);
    issueB(0); issueB(1);

    // ch = 0..5: issue ch+2, wait_group 2
    for (int ch = 0; ch < 6; ++ch) {
        storeA(ch);
        loadA(ch + 2);
        issueB(ch + 2);
        asm volatile("cp.async.wait_group 2;" ::: "memory");
        __syncthreads();
        compute(ch);
    }
    // ch = 6
    storeA(6);
    asm volatile("cp.async.wait_group 1;" ::: "memory");
    __syncthreads();
    compute(6);
    // ch = 7
    storeA(7);
    asm volatile("cp.async.wait_group 0;" ::: "memory");
    __syncthreads();
    compute(7);

    // epilogue
    #pragma unroll
    for (int i = 0; i < 4; ++i) {
        int row = m0 + wm * 64 + i * 16 + (lane >> 2);
        float* o0 = out + ((size_t)g * BSZ + row) * CH + wn * 32 + (lane & 3) * 2;
        #pragma unroll
        for (int j = 0; j < 4; ++j) {
            *(float2*)(o0 + j * 8)          = make_float2(acc[i][j][0], acc[i][j][1]);
            *(float2*)(o0 + 8 * CH + j * 8) = make_float2(acc[i][j][2], acc[i][j][3]);
        }
    }
}

// ---------------- entry ----------------------------------------------------
extern "C" void kernel_launch(void* const* d_in, const int* in_sizes, int n_in,
                              void* d_out, int out_size) {
    const float* x = (const float*)d_in[0];
    const float* w = (const float*)d_in[1];
    if (n_in >= 2 && in_sizes[0] < in_sizes[1]) {
        const float* tmp = x; x = w; w = tmp;
    }
    float* out = (float*)d_out;

    cudaFuncSetAttribute(main_mma, cudaFuncAttributeMaxDynamicSharedMemorySize,
                         SMEM_TOTAL);
    cudaFuncSetAttribute(g_mma, cudaFuncAttributeMaxDynamicSharedMemorySize, 65536);
    cudaFuncSetAttribute(q_mma, cudaFuncAttributeMaxDynamicSharedMemorySize, 65536);

    vsplit<<<GRP * CH * CH / 1024, 256>>>(w);

    dim3 ggrid(3, GRP);
    g_mma<<<ggrid, 256, 65536>>>();

    tinv_kernel<<<GRP, 256>>>();

    dim3 ygrid(CH / 32, GRP);
    y_kernel<<<ygrid, 256>>>(w);

    dim3 qgrid(4, GRP);
    q_mma<<<qgrid, 256, 65536>>>();

    dim3 mgrid(BSZ / BM, GRP);
    main_mma<<<mgrid, 512, SMEM_TOTAL>>>(x, out);
}

// round 10
// speedup vs baseline: 1.1925x; 1.1925x over previous
#include <cuda_runtime.h>
#include <cuda_bf16.h>
#include <cstdint>

#define GRP 16
#define BSZ 8192
#define CH  256

// ---------------- scratch (device globals; no allocation allowed) ----------
__device__ float g_G[GRP * CH * CH];            // G = V^T V (upper blocks)
__device__ float g_Tinv[GRP * 8 * 32 * 32];     // diag-block inverses of R
__device__ __nv_bfloat16 g_Vhi[GRP * CH * CH];  // W split
__device__ __nv_bfloat16 g_Vlo[GRP * CH * CH];
__device__ __nv_bfloat16 g_Yhi[GRP * CH * CH];  // Y split
__device__ __nv_bfloat16 g_Ylo[GRP * CH * CH];
__device__ __nv_bfloat16 g_Qhi[GRP * CH * CH];  // Q split (row-major)
__device__ __nv_bfloat16 g_Qlo[GRP * CH * CH];

__device__ __forceinline__ uint32_t smem_u32(const void* p) {
    uint32_t a;
    asm("{ .reg .u64 t; cvta.to.shared.u64 t, %1; cvt.u32.u64 %0, t; }"
        : "=r"(a) : "l"(p));
    return a;
}

#define LDSM4(r, addr)                                                      \
    asm volatile("ldmatrix.sync.aligned.m8n8.x4.shared.b16 {%0,%1,%2,%3}, [%4];" \
                 : "=r"((r)[0]), "=r"((r)[1]), "=r"((r)[2]), "=r"((r)[3])   \
                 : "r"(addr))
#define LDSM4T(r, addr)                                                     \
    asm volatile("ldmatrix.sync.aligned.m8n8.x4.trans.shared.b16 {%0,%1,%2,%3}, [%4];" \
                 : "=r"((r)[0]), "=r"((r)[1]), "=r"((r)[2]), "=r"((r)[3])   \
                 : "r"(addr))
#define MMA(c, a, b0, b1)                                                   \
    asm volatile("mma.sync.aligned.m16n8k16.row.col.f32.bf16.bf16.f32 "     \
                 "{%0,%1,%2,%3}, {%4,%5,%6,%7}, {%8,%9}, {%0,%1,%2,%3};"    \
                 : "+f"((c)[0]), "+f"((c)[1]), "+f"((c)[2]), "+f"((c)[3])   \
                 : "r"((a)[0]), "r"((a)[1]), "r"((a)[2]), "r"((a)[3]),      \
                   "r"(b0), "r"(b1))
#define CP16(dst, src)                                                      \
    asm volatile("cp.async.cg.shared.global [%0], [%1], 16;"                \
                 :: "r"(dst), "l"(src) : "memory")

__device__ __forceinline__ uint32_t pack_hi(float a, float b) {
    __nv_bfloat16 x = __float2bfloat16(a), y = __float2bfloat16(b);
    return ((uint32_t)__bfloat16_as_ushort(y) << 16) | __bfloat16_as_ushort(x);
}
__device__ __forceinline__ uint32_t pack_lo(float a, float b) {
    __nv_bfloat16 x = __float2bfloat16(a), y = __float2bfloat16(b);
    __nv_bfloat16 lx = __float2bfloat16(a - __bfloat162float(x));
    __nv_bfloat16 ly = __float2bfloat16(b - __bfloat162float(y));
    return ((uint32_t)__bfloat16_as_ushort(ly) << 16) | __bfloat16_as_ushort(lx);
}

// ---------------- vsplit: W -> bf16 hi/lo ----------------------------------
__global__ void vsplit(const float* __restrict__ W) {
    int idx = (blockIdx.x * 256 + threadIdx.x) * 4;
    float4 v = *(const float4*)(W + idx);
    uint2 h, l;
    h.x = pack_hi(v.x, v.y); h.y = pack_hi(v.z, v.w);
    l.x = pack_lo(v.x, v.y); l.y = pack_lo(v.z, v.w);
    *(uint2*)&g_Vhi[idx] = h;
    *(uint2*)&g_Vlo[idx] = l;
}

// ---------------- g_mma: G = V^T V (upper 128x128 tiles, HMMA) -------------
#define GSTRIDE 32768u
__global__ void __launch_bounds__(256) g_mma() {
    extern __shared__ __align__(1024) char sm[];
    const uint32_t sb = smem_u32(sm);
    int t = threadIdx.x, warp = t >> 5, lane = t & 31;
    int wm = warp >> 2, wn = warp & 3;
    int g = blockIdx.y;
    int bx = blockIdx.x;                 // 0:(0,0) 1:(0,128) 2:(128,128)
    int a0 = (bx == 2) ? 128 : 0;
    int b0 = (bx == 0) ? 0 : 128;

    const __nv_bfloat16* Vh = g_Vhi + (size_t)g * CH * CH;
    const __nv_bfloat16* Vl = g_Vlo + (size_t)g * CH * CH;

    int kk = t >> 3, g0 = t & 7;
    auto stage = [&](int chk) {
        uint32_t d = sb + (uint32_t)(chk & 1) * GSTRIDE;
        int krow = chk * 32 + kk;
        #pragma unroll
        for (int gi = 0; gi < 2; ++gi) {
            int gr = g0 + gi * 8;
            uint32_t off = (uint32_t)kk * 256 + (uint32_t)((gr ^ (kk & 7)) << 4);
            CP16(d + off,          Vh + (size_t)krow * CH + a0 + gr * 8);
            CP16(d + 8192  + off,  Vl + (size_t)krow * CH + a0 + gr * 8);
            CP16(d + 16384 + off,  Vh + (size_t)krow * CH + b0 + gr * 8);
            CP16(d + 24576 + off,  Vl + (size_t)krow * CH + b0 + gr * 8);
        }
        asm volatile("cp.async.commit_group;" ::: "memory");
    };

    float acc[4][4][4] = {};
    stage(0);
    for (int ch = 0; ch < 8; ++ch) {
        asm volatile("cp.async.wait_group 0;" ::: "memory");
        __syncthreads();
        if (ch < 7) stage(ch + 1);
        uint32_t buf = sb + (uint32_t)(ch & 1) * GSTRIDE;
        #pragma unroll
        for (int ks = 0; ks < 32; ks += 16) {
            uint32_t ah[4][4], al[4][4];
            #pragma unroll
            for (int i = 0; i < 4; ++i) {
                uint32_t mb = (uint32_t)(wm * 64 + i * 16);
                uint32_t krow = (uint32_t)(ks + (lane & 7) + ((lane >> 4) << 3));
                uint32_t gran = (mb >> 3) + ((lane >> 3) & 1);
                uint32_t addr = buf + krow * 256u + ((gran ^ (krow & 7)) << 4);
                LDSM4T(ah[i], addr);
                LDSM4T(al[i], addr + 8192);
            }
            #pragma unroll
            for (int p = 0; p < 2; ++p) {
                uint32_t bh[4], bl[4];
                uint32_t krow = (uint32_t)(ks + (lane & 15));
                uint32_t gran = (uint32_t)(wn * 4 + p * 2 + (lane >> 4));
                uint32_t addr = buf + 16384 + krow * 256u + ((gran ^ (krow & 7)) << 4);
                LDSM4T(bh, addr);
                LDSM4T(bl, addr + 8192);
                #pragma unroll
                for (int i = 0; i < 4; ++i) {
                    MMA(acc[i][2 * p],     ah[i], bh[0], bh[1]);
                    MMA(acc[i][2 * p],     ah[i], bl[0], bl[1]);
                    MMA(acc[i][2 * p],     al[i], bh[0], bh[1]);
                    MMA(acc[i][2 * p + 1], ah[i], bh[2], bh[3]);
                    MMA(acc[i][2 * p + 1], ah[i], bl[2], bl[3]);
                    MMA(acc[i][2 * p + 1], al[i], bh[2], bh[3]);
                }
            }
        }
    }
    float* Gg = g_G + (size_t)g * CH * CH;
    #pragma unroll
    for (int i = 0; i < 4; ++i) {
        int row = a0 + wm * 64 + i * 16 + (lane >> 2);
        #pragma unroll
        for (int j = 0; j < 4; ++j) {
            int col = b0 + wn * 32 + j * 8 + (lane & 3) * 2;
            *(float2*)&Gg[(size_t)row * CH + col]       = make_float2(acc[i][j][0], acc[i][j][1]);
            *(float2*)&Gg[(size_t)(row + 8) * CH + col] = make_float2(acc[i][j][2], acc[i][j][3]);
        }
    }
}

// ---------------- tinv: invert 32x32 diagonal blocks of R ------------------
__global__ void __launch_bounds__(256) tinv_kernel() {
    int g = blockIdx.x;
    int t = threadIdx.x;
    int kb = t >> 5, j = t & 31;

    __shared__ float Ts[8][32][33];
    __shared__ float bet[CH];

    const float* Gg = g_G + (size_t)g * CH * CH;
    bet[t] = 2.0f / Gg[(size_t)t * CH + t];
    __syncthreads();

    int c0 = kb * 32;
    for (int i = j + 1; i < 32; ++i) Ts[kb][i][j] = 0.f;
    Ts[kb][j][j] = bet[c0 + j];
    for (int i = j - 1; i >= 0; --i) {
        float s = 0.f;
        for (int k = i + 1; k <= j; ++k)
            s += Gg[(size_t)(c0 + i) * CH + c0 + k] * Ts[kb][k][j];
        Ts[kb][i][j] = -bet[c0 + i] * s;
    }
    float* Tg = g_Tinv + ((size_t)g * 8 + kb) * 32 * 32;
    for (int i = 0; i < 32; ++i)
        Tg[i * 32 + j] = Ts[kb][i][j];
}

// ---------------- Y = V R^{-1}: SMEM-resident panel, warp-local phases -----
// Dynamic smem layout (floats):
//   Gu  : 28 strict-upper blocks, each [32][36]   @ 0       (32256 floats)
//   Td  : 8 Tinv blocks,          each [32][36]   @ 32256   (9216)
//   Ys  : [32][264]                               @ 41472   (8448)
//   pre : [32][33]                                @ 49920   (1056)
#define Y_SMEM_FLOATS 50976
#define Y_SMEM_BYTES  (Y_SMEM_FLOATS * 4)
__global__ void __launch_bounds__(256) y_kernel(const float* __restrict__ W) {
    extern __shared__ __align__(128) float S[];
    const uint32_t sb = smem_u32(S);
    int g  = blockIdx.y;
    int r0 = blockIdx.x * 32;
    int t  = threadIdx.x;

    const float* Vg = W + (size_t)g * CH * CH;
    const float* Gg = g_G + (size_t)g * CH * CH;

    // ---- bulk-load strict-upper G panel + Tinv blocks via cp.async
    {
        int rr = t >> 3, c = t & 7;   // one 16B chunk per thread per block
        int p = 0;
        for (int kb = 1; kb < 8; ++kb)
            for (int jc = 0; jc < kb; ++jc, ++p)
                CP16(sb + (uint32_t)(p * 1152 + rr * 36) * 4 + c * 16,
                     Gg + (size_t)(jc * 32 + rr) * CH + kb * 32 + c * 4);
        const float* Tg = g_Tinv + (size_t)g * 8 * 1024;
        for (int kb = 0; kb < 8; ++kb)
            CP16(sb + (uint32_t)(32256 + kb * 1152 + rr * 36) * 4 + c * 16,
                 Tg + (size_t)kb * 1024 + rr * 32 + c * 4);
        asm volatile("cp.async.commit_group;" ::: "memory");
    }

    // ---- prefetch this thread's V values (overlaps with cp.async)
    int r = t >> 3, q = t & 7;
    float4 vv[8];
    #pragma unroll
    for (int kb = 0; kb < 8; ++kb)
        vv[kb] = *(const float4*)&Vg[(size_t)(r0 + r) * CH + kb * 32 + 4 * q];

    asm volatile("cp.async.wait_group 0;" ::: "memory");
    __syncthreads();

    float* Ysr = S + 41472 + r * 264;     // this row's Ys
    float* Prr = S + 49920 + r * 33;      // this row's pre

    // ---- 8 phases; all cross-phase deps are within one warp -> syncwarp only
    for (int kb = 0; kb < 8; ++kb) {
        float a0 = vv[kb].x, a1 = vv[kb].y, a2 = vv[kb].z, a3 = vv[kb].w;
        int pbase = kb * (kb - 1) / 2;
        for (int jc = 0; jc < kb; ++jc) {
            const float* Gb = S + (pbase + jc) * 1152 + 4 * q;
            const float* Yj = Ysr + jc * 32;
            #pragma unroll
            for (int jj = 0; jj < 32; ++jj) {
                float yv = Yj[jj];
                float4 gg = *(const float4*)(Gb + jj * 36);
                a0 -= yv * gg.x;
                a1 -= yv * gg.y;
                a2 -= yv * gg.z;
                a3 -= yv * gg.w;
            }
        }
        Prr[4 * q + 0] = a0;
        Prr[4 * q + 1] = a1;
        Prr[4 * q + 2] = a2;
        Prr[4 * q + 3] = a3;
        __syncwarp();
        const float* Tdb = S + 32256 + kb * 1152 + 4 * q;
        float o0 = 0.f, o1 = 0.f, o2 = 0.f, o3 = 0.f;
        #pragma unroll
        for (int i = 0; i < 32; ++i) {
            float pv = Prr[i];
            float4 tv = *(const float4*)(Tdb + i * 36);
            o0 += pv * tv.x;
            o1 += pv * tv.y;
            o2 += pv * tv.z;
            o3 += pv * tv.w;
        }
        Ysr[kb * 32 + 4 * q + 0] = o0;
        Ysr[kb * 32 + 4 * q + 1] = o1;
        Ysr[kb * 32 + 4 * q + 2] = o2;
        Ysr[kb * 32 + 4 * q + 3] = o3;
        __syncwarp();
    }
    __syncthreads();

    // ---- emit Y as bf16 hi/lo
    for (int e = t; e < 32 * (CH / 2); e += 256) {
        int rr = e >> 7, cc = (e & 127) * 2;
        float v0 = S[41472 + rr * 264 + cc], v1 = S[41472 + rr * 264 + cc + 1];
        size_t idx = ((size_t)g * CH + r0 + rr) * CH + cc;
        *(uint32_t*)&g_Yhi[idx] = pack_hi(v0, v1);
        *(uint32_t*)&g_Ylo[idx] = pack_lo(v0, v1);
    }
}

// ---------------- q_mma: Q = I - Y V^T (128x128 tiles, HMMA) ---------------
#define QSTRIDE 32768u
__global__ void __launch_bounds__(256) q_mma() {
    extern __shared__ __align__(1024) char sm[];
    const uint32_t sb = smem_u32(sm);
    int t = threadIdx.x, warp = t >> 5, lane = t & 31;
    int wm = warp >> 2, wn = warp & 3;
    int g = blockIdx.y;
    int a0 = (blockIdx.x >> 1) * 128, b0 = (blockIdx.x & 1) * 128;

    const __nv_bfloat16* Yh = g_Yhi + (size_t)g * CH * CH;
    const __nv_bfloat16* Yl = g_Ylo + (size_t)g * CH * CH;
    const __nv_bfloat16* Vh = g_Vhi + (size_t)g * CH * CH;
    const __nv_bfloat16* Vl = g_Vlo + (size_t)g * CH * CH;

    int row = t >> 1, gp = (t & 1) * 2;
    auto stage = [&](int chk) {
        uint32_t d = sb + (uint32_t)(chk & 1) * QSTRIDE;
        int k0 = chk * 32;
        #pragma unroll
        for (int gi = 0; gi < 2; ++gi) {
            int gr = gp + gi;
            uint32_t off = (uint32_t)row * 64 + (uint32_t)((gr ^ ((row >> 1) & 3)) << 4);
            CP16(d + off,          Yh + (size_t)(a0 + row) * CH + k0 + gr * 8);
            CP16(d + 8192  + off,  Yl + (size_t)(a0 + row) * CH + k0 + gr * 8);
            CP16(d + 16384 + off,  Vh + (size_t)(b0 + row) * CH + k0 + gr * 8);
            CP16(d + 24576 + off,  Vl + (size_t)(b0 + row) * CH + k0 + gr * 8);
        }
        asm volatile("cp.async.commit_group;" ::: "memory");
    };

    float acc[4][4][4] = {};
    stage(0);
    for (int ch = 0; ch < 8; ++ch) {
        asm volatile("cp.async.wait_group 0;" ::: "memory");
        __syncthreads();
        if (ch < 7) stage(ch + 1);
        uint32_t buf = sb + (uint32_t)(ch & 1) * QSTRIDE;
        #pragma unroll
        for (int ks = 0; ks < 32; ks += 16) {
            uint32_t ah[4][4], al[4][4];
            #pragma unroll
            for (int i = 0; i < 4; ++i) {
                uint32_t mrow = (uint32_t)(wm * 64 + i * 16 + (lane & 15));
                uint32_t gran = (uint32_t)((ks >> 3) + (lane >> 4));
                uint32_t addr = buf + mrow * 64u + ((gran ^ ((mrow >> 1) & 3)) << 4);
                LDSM4(ah[i], addr);
                LDSM4(al[i], addr + 8192);
            }
            #pragma unroll
            for (int p = 0; p < 2; ++p) {
                uint32_t bh[4], bl[4];
                uint32_t nrow = (uint32_t)(wn * 32 + p * 16 + (lane & 7) + ((lane >> 4) << 3));
                uint32_t gran = (uint32_t)((ks >> 3) + ((lane >> 3) & 1));
                uint32_t addr = buf + 16384 + nrow * 64u + ((gran ^ ((nrow >> 1) & 3)) << 4);
                LDSM4(bh, addr);
                LDSM4(bl, addr + 8192);
                #pragma unroll
                for (int i = 0; i < 4; ++i) {
                    MMA(acc[i][2 * p],     ah[i], bh[0], bh[1]);
                    MMA(acc[i][2 * p],     ah[i], bl[0], bl[1]);
                    MMA(acc[i][2 * p],     al[i], bh[0], bh[1]);
                    MMA(acc[i][2 * p + 1], ah[i], bh[2], bh[3]);
                    MMA(acc[i][2 * p + 1], ah[i], bl[2], bl[3]);
                    MMA(acc[i][2 * p + 1], al[i], bh[2], bh[3]);
                }
            }
        }
    }
    #pragma unroll
    for (int i = 0; i < 4; ++i) {
        int rr = a0 + wm * 64 + i * 16 + (lane >> 2);
        #pragma unroll
        for (int j = 0; j < 4; ++j) {
            int cc = b0 + wn * 32 + j * 8 + (lane & 3) * 2;
            float v0 = (rr == cc     ? 1.f : 0.f) - acc[i][j][0];
            float v1 = (rr == cc + 1 ? 1.f : 0.f) - acc[i][j][1];
            float v2 = (rr + 8 == cc     ? 1.f : 0.f) - acc[i][j][2];
            float v3 = (rr + 8 == cc + 1 ? 1.f : 0.f) - acc[i][j][3];
            size_t i0 = ((size_t)g * CH + rr) * CH + cc;
            size_t i1 = ((size_t)g * CH + rr + 8) * CH + cc;
            *(uint32_t*)&g_Qhi[i0] = pack_hi(v0, v1);
            *(uint32_t*)&g_Qlo[i0] = pack_lo(v0, v1);
            *(uint32_t*)&g_Qhi[i1] = pack_hi(v2, v3);
            *(uint32_t*)&g_Qlo[i1] = pack_lo(v2, v3);
        }
    }
}

// ---------------- out = x @ Q via mma.sync bf16 hi/lo split (R8 config) ----
#define BM 128
#define BN 256
#define BK 32
#define SA_H 0u
#define SA_L 10240u
#define SB_H 20480u
#define SB_L 36864u
#define SBUF 53248u
#define SMEM_TOTAL (2u * SBUF)

__global__ void __launch_bounds__(512, 1) main_mma(const float* __restrict__ X,
                                                   float* __restrict__ out) {
    extern __shared__ __align__(1024) char sm[];
    const uint32_t sbase = smem_u32(sm);

    int t = threadIdx.x;
    int warp = t >> 5, lane = t & 31;
    int wm = warp >> 3, wn = warp & 7;      // warp tile 64m x 32n
    int g = blockIdx.y;
    int m0 = blockIdx.x * BM;

    const float* Xg = X + ((size_t)g * BSZ + m0) * CH;
    const __nv_bfloat16* Qh = g_Qhi + (size_t)g * CH * CH;
    const __nv_bfloat16* Ql = g_Qlo + (size_t)g * CH * CH;

    int ar = t >> 2, ac = (t & 3) * 8;
    int brow = t >> 4, bg0 = t & 15;

    float acc[4][4][4] = {};
    float4 xa[2];

    auto loadA = [&](int ch) {
        xa[0] = *(const float4*)(Xg + (size_t)ar * CH + ch * BK + ac);
        xa[1] = *(const float4*)(Xg + (size_t)ar * CH + ch * BK + ac + 4);
    };
    auto issueB = [&](int ch) {
        uint32_t d = sbase + (uint32_t)(ch & 1) * SBUF;
        #pragma unroll
        for (int gi = 0; gi < 2; ++gi) {
            int gr = bg0 + gi * 16;
            uint32_t off = (uint32_t)brow * 512 + (uint32_t)((gr ^ (brow & 7)) << 4);
            const __nv_bfloat16* sh = Qh + (size_t)(ch * BK + brow) * CH + gr * 8;
            const __nv_bfloat16* sl = Ql + (size_t)(ch * BK + brow) * CH + gr * 8;
            CP16(d + SB_H + off, sh);
            CP16(d + SB_L + off, sl);
        }
        asm volatile("cp.async.commit_group;" ::: "memory");
    };
    auto storeA = [&](int ch) {
        char* p = sm + (ch & 1) * SBUF;
        float f[8] = {xa[0].x, xa[0].y, xa[0].z, xa[0].w,
                      xa[1].x, xa[1].y, xa[1].z, xa[1].w};
        uint32_t h[4], l[4];
        #pragma unroll
        for (int i = 0; i < 4; ++i) {
            h[i] = pack_hi(f[2 * i], f[2 * i + 1]);
            l[i] = pack_lo(f[2 * i], f[2 * i + 1]);
        }
        uint32_t ao = ar * 80u + ac * 2u;
        *(uint4*)(p + SA_H + ao) = make_uint4(h[0], h[1], h[2], h[3]);
        *(uint4*)(p + SA_L + ao) = make_uint4(l[0], l[1], l[2], l[3]);
    };

    loadA(0);
    issueB(0);

    for (int ch = 0; ch < CH / BK; ++ch) {
        asm volatile("cp.async.wait_group 0;" ::: "memory");
        storeA(ch);
        __syncthreads();
        if (ch + 1 < CH / BK) { loadA(ch + 1); issueB(ch + 1); }

        uint32_t sb = sbase + (uint32_t)(ch & 1) * SBUF;
        #pragma unroll
        for (int ks = 0; ks < BK; ks += 16) {
            uint32_t ah[4][4], al[4][4];
            #pragma unroll
            for (int i = 0; i < 4; ++i) {
                uint32_t mrow = (uint32_t)(wm * 64 + i * 16 + (lane & 15));
                uint32_t kcol = (uint32_t)(ks + (lane >> 4) * 8);
                uint32_t addr = sb + SA_H + mrow * 80u + kcol * 2u;
                LDSM4(ah[i], addr);
                LDSM4(al[i], addr + (SA_L - SA_H));
            }
            #pragma unroll
            for (int p = 0; p < 2; ++p) {
                uint32_t bh[4], bl[4];
                uint32_t krow = (uint32_t)(ks + (lane & 15));
                uint32_t gran = (uint32_t)(wn * 4 + p * 2 + (lane >> 4));
                uint32_t addr = sb + SB_H + krow * 512u + ((gran ^ (krow & 7)) << 4);
                LDSM4T(bh, addr);
                LDSM4T(bl, addr + (SB_L - SB_H));
                #pragma unroll
                for (int i = 0; i < 4; ++i) {
                    MMA(acc[i][2 * p],     ah[i], bh[0], bh[1]);
                    MMA(acc[i][2 * p],     ah[i], bl[0], bl[1]);
                    MMA(acc[i][2 * p],     al[i], bh[0], bh[1]);
                    MMA(acc[i][2 * p + 1], ah[i], bh[2], bh[3]);
                    MMA(acc[i][2 * p + 1], ah[i], bl[2], bl[3]);
                    MMA(acc[i][2 * p + 1], al[i], bh[2], bh[3]);
                }
            }
        }
    }

    // epilogue
    #pragma unroll
    for (int i = 0; i < 4; ++i) {
        int row = m0 + wm * 64 + i * 16 + (lane >> 2);
        float* o0 = out + ((size_t)g * BSZ + row) * CH + wn * 32 + (lane & 3) * 2;
        #pragma unroll
        for (int j = 0; j < 4; ++j) {
            *(float2*)(o0 + j * 8)          = make_float2(acc[i][j][0], acc[i][j][1]);
            *(float2*)(o0 + 8 * CH + j * 8) = make_float2(acc[i][j][2], acc[i][j][3]);
        }
    }
}

// ---------------- entry ----------------------------------------------------
extern "C" void kernel_launch(void* const* d_in, const int* in_sizes, int n_in,
                              void* d_out, int out_size) {
    const float* x = (const float*)d_in[0];
    const float* w = (const float*)d_in[1];
    if (n_in >= 2 && in_sizes[0] < in_sizes[1]) {
        const float* tmp = x; x = w; w = tmp;
    }
    float* out = (float*)d_out;

    cudaFuncSetAttribute(main_mma, cudaFuncAttributeMaxDynamicSharedMemorySize,
                         SMEM_TOTAL);
    cudaFuncSetAttribute(g_mma, cudaFuncAttributeMaxDynamicSharedMemorySize, 65536);
    cudaFuncSetAttribute(q_mma, cudaFuncAttributeMaxDynamicSharedMemorySize, 65536);
    cudaFuncSetAttribute(y_kernel, cudaFuncAttributeMaxDynamicSharedMemorySize,
                         Y_SMEM_BYTES);

    vsplit<<<GRP * CH * CH / 1024, 256>>>(w);

    dim3 ggrid(3, GRP);
    g_mma<<<ggrid, 256, 65536>>>();

    tinv_kernel<<<GRP, 256>>>();

    dim3 ygrid(CH / 32, GRP);
    y_kernel<<<ygrid, 256, Y_SMEM_BYTES>>>(w);

    dim3 qgrid(4, GRP);
    q_mma<<<qgrid, 256, 65536>>>();

    dim3 mgrid(BSZ / BM, GRP);
    main_mma<<<mgrid, 512, SMEM_TOTAL>>>(x, out);
}

// round 11
// speedup vs baseline: 1.2041x; 1.0097x over previous
#include <cuda_runtime.h>
#include <cuda_bf16.h>
#include <cstdint>

#define GRP 16
#define BSZ 8192
#define CH  256

// ---------------- scratch (device globals; no allocation allowed) ----------
__device__ float g_G[GRP * CH * CH];            // G = V^T V (upper blocks)
__device__ float g_Tinv[GRP * 8 * 32 * 32];     // diag-block inverses of R
__device__ __nv_bfloat16 g_Vhi[GRP * CH * CH];  // W split
__device__ __nv_bfloat16 g_Vlo[GRP * CH * CH];
__device__ __nv_bfloat16 g_Yhi[GRP * CH * CH];  // Y split
__device__ __nv_bfloat16 g_Ylo[GRP * CH * CH];
// Q^T hi/lo as pre-swizzled SMEM images: [GRP][8 chunks][16384 bytes]
__device__ unsigned char g_Qhi_sw[GRP * 8 * 16384];
__device__ unsigned char g_Qlo_sw[GRP * 8 * 16384];

__device__ __forceinline__ uint32_t smem_u32(const void* p) {
    uint32_t a;
    asm("{ .reg .u64 t; cvta.to.shared.u64 t, %1; cvt.u32.u64 %0, t; }"
        : "=r"(a) : "l"(p));
    return a;
}

#define LDSM4(r, addr)                                                      \
    asm volatile("ldmatrix.sync.aligned.m8n8.x4.shared.b16 {%0,%1,%2,%3}, [%4];" \
                 : "=r"((r)[0]), "=r"((r)[1]), "=r"((r)[2]), "=r"((r)[3])   \
                 : "r"(addr))
#define LDSM4T(r, addr)                                                     \
    asm volatile("ldmatrix.sync.aligned.m8n8.x4.trans.shared.b16 {%0,%1,%2,%3}, [%4];" \
                 : "=r"((r)[0]), "=r"((r)[1]), "=r"((r)[2]), "=r"((r)[3])   \
                 : "r"(addr))
#define MMA(c, a, b0, b1)                                                   \
    asm volatile("mma.sync.aligned.m16n8k16.row.col.f32.bf16.bf16.f32 "     \
                 "{%0,%1,%2,%3}, {%4,%5,%6,%7}, {%8,%9}, {%0,%1,%2,%3};"    \
                 : "+f"((c)[0]), "+f"((c)[1]), "+f"((c)[2]), "+f"((c)[3])   \
                 : "r"((a)[0]), "r"((a)[1]), "r"((a)[2]), "r"((a)[3]),      \
                   "r"(b0), "r"(b1))
#define CP16(dst, src)                                                      \
    asm volatile("cp.async.cg.shared.global [%0], [%1], 16;"                \
                 :: "r"(dst), "l"(src) : "memory")

__device__ __forceinline__ void mbar_wait(uint32_t mbar, uint32_t parity) {
    asm volatile(
        "{\n\t.reg .pred P;\n"
        "LW_%=:\n\t"
        "mbarrier.try_wait.parity.acquire.cta.shared::cta.b64 P, [%0], %1, 0x989680;\n\t"
        "@P bra LD_%=;\n\t"
        "bra LW_%=;\n"
        "LD_%=:\n\t}"
        :: "r"(mbar), "r"(parity) : "memory");
}

__device__ __forceinline__ uint32_t pack_hi(float a, float b) {
    __nv_bfloat16 x = __float2bfloat16(a), y = __float2bfloat16(b);
    return ((uint32_t)__bfloat16_as_ushort(y) << 16) | __bfloat16_as_ushort(x);
}
__device__ __forceinline__ uint32_t pack_lo(float a, float b) {
    __nv_bfloat16 x = __float2bfloat16(a), y = __float2bfloat16(b);
    __nv_bfloat16 lx = __float2bfloat16(a - __bfloat162float(x));
    __nv_bfloat16 ly = __float2bfloat16(b - __bfloat162float(y));
    return ((uint32_t)__bfloat16_as_ushort(ly) << 16) | __bfloat16_as_ushort(lx);
}

// ---------------- vsplit: W -> bf16 hi/lo ----------------------------------
__global__ void vsplit(const float* __restrict__ W) {
    int idx = (blockIdx.x * 256 + threadIdx.x) * 4;
    float4 v = *(const float4*)(W + idx);
    uint2 h, l;
    h.x = pack_hi(v.x, v.y); h.y = pack_hi(v.z, v.w);
    l.x = pack_lo(v.x, v.y); l.y = pack_lo(v.z, v.w);
    *(uint2*)&g_Vhi[idx] = h;
    *(uint2*)&g_Vlo[idx] = l;
}

// ---------------- g_mma: G = V^T V (upper 128x128 tiles, HMMA) -------------
#define GSTRIDE 32768u
__global__ void __launch_bounds__(256) g_mma() {
    extern __shared__ __align__(1024) char sm[];
    const uint32_t sb = smem_u32(sm);
    int t = threadIdx.x, warp = t >> 5, lane = t & 31;
    int wm = warp >> 2, wn = warp & 3;
    int g = blockIdx.y;
    int bx = blockIdx.x;                 // 0:(0,0) 1:(0,128) 2:(128,128)
    int a0 = (bx == 2) ? 128 : 0;
    int b0 = (bx == 0) ? 0 : 128;

    const __nv_bfloat16* Vh = g_Vhi + (size_t)g * CH * CH;
    const __nv_bfloat16* Vl = g_Vlo + (size_t)g * CH * CH;

    int kk = t >> 3, g0 = t & 7;
    auto stage = [&](int chk) {
        uint32_t d = sb + (uint32_t)(chk & 1) * GSTRIDE;
        int krow = chk * 32 + kk;
        #pragma unroll
        for (int gi = 0; gi < 2; ++gi) {
            int gr = g0 + gi * 8;
            uint32_t off = (uint32_t)kk * 256 + (uint32_t)((gr ^ (kk & 7)) << 4);
            CP16(d + off,          Vh + (size_t)krow * CH + a0 + gr * 8);
            CP16(d + 8192  + off,  Vl + (size_t)krow * CH + a0 + gr * 8);
            CP16(d + 16384 + off,  Vh + (size_t)krow * CH + b0 + gr * 8);
            CP16(d + 24576 + off,  Vl + (size_t)krow * CH + b0 + gr * 8);
        }
        asm volatile("cp.async.commit_group;" ::: "memory");
    };

    float acc[4][4][4] = {};
    stage(0);
    for (int ch = 0; ch < 8; ++ch) {
        asm volatile("cp.async.wait_group 0;" ::: "memory");
        __syncthreads();
        if (ch < 7) stage(ch + 1);
        uint32_t buf = sb + (uint32_t)(ch & 1) * GSTRIDE;
        #pragma unroll
        for (int ks = 0; ks < 32; ks += 16) {
            uint32_t ah[4][4], al[4][4];
            #pragma unroll
            for (int i = 0; i < 4; ++i) {
                uint32_t mb = (uint32_t)(wm * 64 + i * 16);
                uint32_t krow = (uint32_t)(ks + (lane & 7) + ((lane >> 4) << 3));
                uint32_t gran = (mb >> 3) + ((lane >> 3) & 1);
                uint32_t addr = buf + krow * 256u + ((gran ^ (krow & 7)) << 4);
                LDSM4T(ah[i], addr);
                LDSM4T(al[i], addr + 8192);
            }
            #pragma unroll
            for (int p = 0; p < 2; ++p) {
                uint32_t bh[4], bl[4];
                uint32_t krow = (uint32_t)(ks + (lane & 15));
                uint32_t gran = (uint32_t)(wn * 4 + p * 2 + (lane >> 4));
                uint32_t addr = buf + 16384 + krow * 256u + ((gran ^ (krow & 7)) << 4);
                LDSM4T(bh, addr);
                LDSM4T(bl, addr + 8192);
                #pragma unroll
                for (int i = 0; i < 4; ++i) {
                    MMA(acc[i][2 * p],     ah[i], bh[0], bh[1]);
                    MMA(acc[i][2 * p],     ah[i], bl[0], bl[1]);
                    MMA(acc[i][2 * p],     al[i], bh[0], bh[1]);
                    MMA(acc[i][2 * p + 1], ah[i], bh[2], bh[3]);
                    MMA(acc[i][2 * p + 1], ah[i], bl[2], bl[3]);
                    MMA(acc[i][2 * p + 1], al[i], bh[2], bh[3]);
                }
            }
        }
    }
    float* Gg = g_G + (size_t)g * CH * CH;
    #pragma unroll
    for (int i = 0; i < 4; ++i) {
        int row = a0 + wm * 64 + i * 16 + (lane >> 2);
        #pragma unroll
        for (int j = 0; j < 4; ++j) {
            int col = b0 + wn * 32 + j * 8 + (lane & 3) * 2;
            *(float2*)&Gg[(size_t)row * CH + col]       = make_float2(acc[i][j][0], acc[i][j][1]);
            *(float2*)&Gg[(size_t)(row + 8) * CH + col] = make_float2(acc[i][j][2], acc[i][j][3]);
        }
    }
}

// ---------------- tinv: invert 32x32 diagonal blocks of R (SMEM-staged) ----
#define TINV_SMEM ((8448 + 8448 + 256) * 4)
__global__ void __launch_bounds__(256) tinv_kernel() {
    extern __shared__ __align__(16) float S[];
    float* Gd  = S;            // 8 blocks [32][33]
    float* Ts  = S + 8448;     // 8 blocks [32][33]
    float* bet = S + 16896;

    int g = blockIdx.x;
    int t = threadIdx.x;
    const float* Gg = g_G + (size_t)g * CH * CH;

    for (int e = t; e < 8192; e += 256) {
        int kb = e >> 10, i = (e >> 5) & 31, k = e & 31;
        Gd[kb * 1056 + i * 33 + k] = Gg[(size_t)(kb * 32 + i) * CH + kb * 32 + k];
    }
    bet[t] = 2.0f / Gg[(size_t)t * CH + t];
    __syncthreads();

    int kb = t >> 5, j = t & 31;
    int c0 = kb * 32;
    float* Tb = Ts + kb * 1056;
    const float* Gb = Gd + kb * 1056;
    for (int i = j + 1; i < 32; ++i) Tb[i * 33 + j] = 0.f;
    Tb[j * 33 + j] = bet[c0 + j];
    for (int i = j - 1; i >= 0; --i) {
        float s = 0.f;
        for (int k = i + 1; k <= j; ++k)
            s += Gb[i * 33 + k] * Tb[k * 33 + j];
        Tb[i * 33 + j] = -bet[c0 + i] * s;
    }
    __syncthreads();
    float* Tg = g_Tinv + ((size_t)g * 8 + kb) * 1024;
    for (int i = 0; i < 32; ++i)
        Tg[i * 32 + j] = Tb[i * 33 + j];
}

// ---------------- Y = V R^{-1}: SMEM panel, 64 compute threads -------------
// Dynamic smem (floats):
//   Gu  : 28 blocks [32][36]  @ 0      (32256)
//   Td  : 8 blocks  [32][36]  @ 32256  (9216)
//   Ys  : [32][264]           @ 41472  (8448)   (initialized with V)
//   pre : [32][33]            @ 49920  (1056)
#define Y_SMEM_FLOATS 50976
#define Y_SMEM_BYTES  (Y_SMEM_FLOATS * 4)
__global__ void __launch_bounds__(256) y_kernel(const float* __restrict__ W) {
    extern __shared__ __align__(128) float S[];
    const uint32_t sb = smem_u32(S);
    int g  = blockIdx.y;
    int r0 = blockIdx.x * 32;
    int t  = threadIdx.x;

    const float* Vg = W + (size_t)g * CH * CH;
    const float* Gg = g_G + (size_t)g * CH * CH;

    // bulk-load strict-upper G panel + Tinv + V(->Ys) via cp.async
    {
        int rr = t >> 3, c = t & 7;
        int p = 0;
        for (int kb = 1; kb < 8; ++kb)
            for (int jc = 0; jc < kb; ++jc, ++p)
                CP16(sb + (uint32_t)(p * 1152 + rr * 36) * 4 + c * 16,
                     Gg + (size_t)(jc * 32 + rr) * CH + kb * 32 + c * 4);
        const float* Tg = g_Tinv + (size_t)g * 8 * 1024;
        for (int kb = 0; kb < 8; ++kb)
            CP16(sb + (uint32_t)(32256 + kb * 1152 + rr * 36) * 4 + c * 16,
                 Tg + (size_t)kb * 1024 + rr * 32 + c * 4);
        // Ys init = V rows (32 rows x 64 16B-chunks)
        int vr = t >> 3;                 // 0..31 row
        for (int cc = c; cc < 64; cc += 8)
            CP16(sb + (uint32_t)(41472 + vr * 264) * 4 + cc * 16,
                 Vg + (size_t)(r0 + vr) * CH + cc * 4);
        asm volatile("cp.async.commit_group;" ::: "memory");
        asm volatile("cp.async.wait_group 0;" ::: "memory");
    }
    __syncthreads();

    if (t < 64) {
        int r2 = t >> 3, q = t & 7;     // 4 rows per thread: r2 + 8*ri
        for (int kb = 0; kb < 8; ++kb) {
            int c0 = kb * 32;
            float a[4][4];
            #pragma unroll
            for (int ri = 0; ri < 4; ++ri) {
                float4 v = *(const float4*)(S + 41472 + (r2 + 8 * ri) * 264 + c0 + 4 * q);
                a[ri][0] = v.x; a[ri][1] = v.y; a[ri][2] = v.z; a[ri][3] = v.w;
            }
            int pbase = kb * (kb - 1) / 2;
            for (int jc = 0; jc < kb; ++jc) {
                const float* Gb = S + (pbase + jc) * 1152 + 4 * q;
                int j0 = jc * 32;
                #pragma unroll
                for (int jj = 0; jj < 32; ++jj) {
                    float4 gg = *(const float4*)(Gb + jj * 36);
                    #pragma unroll
                    for (int ri = 0; ri < 4; ++ri) {
                        float yv = S[41472 + (r2 + 8 * ri) * 264 + j0 + jj];
                        a[ri][0] -= yv * gg.x;
                        a[ri][1] -= yv * gg.y;
                        a[ri][2] -= yv * gg.z;
                        a[ri][3] -= yv * gg.w;
                    }
                }
            }
            #pragma unroll
            for (int ri = 0; ri < 4; ++ri) {
                float* Pr = S + 49920 + (r2 + 8 * ri) * 33;
                Pr[4 * q + 0] = a[ri][0];
                Pr[4 * q + 1] = a[ri][1];
                Pr[4 * q + 2] = a[ri][2];
                Pr[4 * q + 3] = a[ri][3];
            }
            __syncwarp();
            const float* Tdb = S + 32256 + kb * 1152 + 4 * q;
            float o[4][4] = {};
            #pragma unroll
            for (int i = 0; i < 32; ++i) {
                float4 tv = *(const float4*)(Tdb + i * 36);
                #pragma unroll
                for (int ri = 0; ri < 4; ++ri) {
                    float pv = S[49920 + (r2 + 8 * ri) * 33 + i];
                    o[ri][0] += pv * tv.x;
                    o[ri][1] += pv * tv.y;
                    o[ri][2] += pv * tv.z;
                    o[ri][3] += pv * tv.w;
                }
            }
            #pragma unroll
            for (int ri = 0; ri < 4; ++ri) {
                float* Yr = S + 41472 + (r2 + 8 * ri) * 264 + c0 + 4 * q;
                Yr[0] = o[ri][0]; Yr[1] = o[ri][1];
                Yr[2] = o[ri][2]; Yr[3] = o[ri][3];
            }
            __syncwarp();
        }
    }
    __syncthreads();

    for (int e = t; e < 32 * (CH / 2); e += 256) {
        int rr = e >> 7, cc = (e & 127) * 2;
        float v0 = S[41472 + rr * 264 + cc], v1 = S[41472 + rr * 264 + cc + 1];
        size_t idx = ((size_t)g * CH + r0 + rr) * CH + cc;
        *(uint32_t*)&g_Yhi[idx] = pack_hi(v0, v1);
        *(uint32_t*)&g_Ylo[idx] = pack_lo(v0, v1);
    }
}

// ---------------- q_mma: Q = I - Y V^T, emits pre-swizzled Q images --------
#define QSTRIDE 32768u
__global__ void __launch_bounds__(256) q_mma() {
    extern __shared__ __align__(1024) char sm[];
    const uint32_t sb = smem_u32(sm);
    int t = threadIdx.x, warp = t >> 5, lane = t & 31;
    int wm = warp >> 2, wn = warp & 3;
    int g = blockIdx.y;
    int a0 = (blockIdx.x >> 1) * 128, b0 = (blockIdx.x & 1) * 128;

    const __nv_bfloat16* Yh = g_Yhi + (size_t)g * CH * CH;
    const __nv_bfloat16* Yl = g_Ylo + (size_t)g * CH * CH;
    const __nv_bfloat16* Vh = g_Vhi + (size_t)g * CH * CH;
    const __nv_bfloat16* Vl = g_Vlo + (size_t)g * CH * CH;

    int row = t >> 1, gp = (t & 1) * 2;
    auto stage = [&](int chk) {
        uint32_t d = sb + (uint32_t)(chk & 1) * QSTRIDE;
        int k0 = chk * 32;
        #pragma unroll
        for (int gi = 0; gi < 2; ++gi) {
            int gr = gp + gi;
            uint32_t off = (uint32_t)row * 64 + (uint32_t)((gr ^ ((row >> 1) & 3)) << 4);
            CP16(d + off,          Yh + (size_t)(a0 + row) * CH + k0 + gr * 8);
            CP16(d + 8192  + off,  Yl + (size_t)(a0 + row) * CH + k0 + gr * 8);
            CP16(d + 16384 + off,  Vh + (size_t)(b0 + row) * CH + k0 + gr * 8);
            CP16(d + 24576 + off,  Vl + (size_t)(b0 + row) * CH + k0 + gr * 8);
        }
        asm volatile("cp.async.commit_group;" ::: "memory");
    };

    float acc[4][4][4] = {};
    stage(0);
    for (int ch = 0; ch < 8; ++ch) {
        asm volatile("cp.async.wait_group 0;" ::: "memory");
        __syncthreads();
        if (ch < 7) stage(ch + 1);
        uint32_t buf = sb + (uint32_t)(ch & 1) * QSTRIDE;
        #pragma unroll
        for (int ks = 0; ks < 32; ks += 16) {
            uint32_t ah[4][4], al[4][4];
            #pragma unroll
            for (int i = 0; i < 4; ++i) {
                uint32_t mrow = (uint32_t)(wm * 64 + i * 16 + (lane & 15));
                uint32_t gran = (uint32_t)((ks >> 3) + (lane >> 4));
                uint32_t addr = buf + mrow * 64u + ((gran ^ ((mrow >> 1) & 3)) << 4);
                LDSM4(ah[i], addr);
                LDSM4(al[i], addr + 8192);
            }
            #pragma unroll
            for (int p = 0; p < 2; ++p) {
                uint32_t bh[4], bl[4];
                uint32_t nrow = (uint32_t)(wn * 32 + p * 16 + (lane & 7) + ((lane >> 4) << 3));
                uint32_t gran = (uint32_t)((ks >> 3) + ((lane >> 3) & 1));
                uint32_t addr = buf + 16384 + nrow * 64u + ((gran ^ ((nrow >> 1) & 3)) << 4);
                LDSM4(bh, addr);
                LDSM4(bl, addr + 8192);
                #pragma unroll
                for (int i = 0; i < 4; ++i) {
                    MMA(acc[i][2 * p],     ah[i], bh[0], bh[1]);
                    MMA(acc[i][2 * p],     ah[i], bl[0], bl[1]);
                    MMA(acc[i][2 * p],     al[i], bh[0], bh[1]);
                    MMA(acc[i][2 * p + 1], ah[i], bh[2], bh[3]);
                    MMA(acc[i][2 * p + 1], ah[i], bl[2], bl[3]);
                    MMA(acc[i][2 * p + 1], al[i], bh[2], bh[3]);
                }
            }
        }
    }
    // epilogue: write swizzled global images
    unsigned char* QH = g_Qhi_sw + (size_t)g * 8 * 16384;
    unsigned char* QL = g_Qlo_sw + (size_t)g * 8 * 16384;
    #pragma unroll
    for (int i = 0; i < 4; ++i) {
        int rr = a0 + wm * 64 + i * 16 + (lane >> 2);
        #pragma unroll
        for (int j = 0; j < 4; ++j) {
            int cc = b0 + wn * 32 + j * 8 + (lane & 3) * 2;
            float v0 = (rr == cc     ? 1.f : 0.f) - acc[i][j][0];
            float v1 = (rr == cc + 1 ? 1.f : 0.f) - acc[i][j][1];
            float v2 = (rr + 8 == cc     ? 1.f : 0.f) - acc[i][j][2];
            float v3 = (rr + 8 == cc + 1 ? 1.f : 0.f) - acc[i][j][3];
            int gran = cc >> 3, sub = (cc & 7) * 2;
            #pragma unroll
            for (int rh = 0; rh < 2; ++rh) {
                int k = rr + rh * 8;
                int chunk = k >> 5, krw = k & 31;
                size_t off = (size_t)chunk * 16384 + krw * 512 +
                             ((gran ^ (krw & 7)) << 4) + sub;
                *(uint32_t*)(QH + off) = pack_hi(rh ? v2 : v0, rh ? v3 : v1);
                *(uint32_t*)(QL + off) = pack_lo(rh ? v2 : v0, rh ? v3 : v1);
            }
        }
    }
}

// ---------------- out = x @ Q: mma.sync + cp.async.bulk B ------------------
#define BM 128
#define BN 256
#define BK 32
#define SA_H 0u
#define SA_L 10240u
#define SB_H 20480u
#define SB_L 36864u
#define SBUF 53248u
#define SMEM_TOTAL (2u * SBUF)

__global__ void __launch_bounds__(512, 1) main_mma(const float* __restrict__ X,
                                                   float* __restrict__ out) {
    extern __shared__ __align__(1024) char sm[];
    __shared__ __align__(8) uint64_t mbars[2];
    const uint32_t sbase = smem_u32(sm);
    const uint32_t mb_base = smem_u32(mbars);

    int t = threadIdx.x;
    int warp = t >> 5, lane = t & 31;
    int wm = warp >> 3, wn = warp & 7;      // warp tile 64m x 32n
    int g = blockIdx.y;
    int m0 = blockIdx.x * BM;

    const float* Xg = X + ((size_t)g * BSZ + m0) * CH;
    const unsigned char* QH = g_Qhi_sw + (size_t)g * 8 * 16384;
    const unsigned char* QL = g_Qlo_sw + (size_t)g * 8 * 16384;

    if (t == 0) {
        asm volatile("mbarrier.init.shared.b64 [%0], 1;" :: "r"(mb_base) : "memory");
        asm volatile("mbarrier.init.shared.b64 [%0], 1;" :: "r"(mb_base + 8) : "memory");
    }
    __syncthreads();

    int ar = t >> 2, ac = (t & 3) * 8;

    float acc[4][4][4] = {};
    float4 xa[2];

    auto loadA = [&](int ch) {
        xa[0] = *(const float4*)(Xg + (size_t)ar * CH + ch * BK + ac);
        xa[1] = *(const float4*)(Xg + (size_t)ar * CH + ch * BK + ac + 4);
    };
    auto issueB = [&](int ch) {   // call with t == 0 only
        uint32_t mbar = mb_base + (uint32_t)(ch & 1) * 8;
        uint32_t dH = sbase + (uint32_t)(ch & 1) * SBUF + SB_H;
        uint32_t dL = sbase + (uint32_t)(ch & 1) * SBUF + SB_L;
        const unsigned char* sH = QH + (size_t)ch * 16384;
        const unsigned char* sL = QL + (size_t)ch * 16384;
        asm volatile("mbarrier.arrive.expect_tx.shared.b64 _, [%0], %1;"
                     :: "r"(mbar), "r"(32768u) : "memory");
        asm volatile("cp.async.bulk.shared::cluster.global.mbarrier::complete_tx::bytes "
                     "[%0], [%1], %2, [%3];"
                     :: "r"(dH), "l"(sH), "r"(16384u), "r"(mbar) : "memory");
        asm volatile("cp.async.bulk.shared::cluster.global.mbarrier::complete_tx::bytes "
                     "[%0], [%1], %2, [%3];"
                     :: "r"(dL), "l"(sL), "r"(16384u), "r"(mbar) : "memory");
    };
    auto storeA = [&](int ch) {
        char* p = sm + (ch & 1) * SBUF;
        float f[8] = {xa[0].x, xa[0].y, xa[0].z, xa[0].w,
                      xa[1].x, xa[1].y, xa[1].z, xa[1].w};
        uint32_t h[4], l[4];
        #pragma unroll
        for (int i = 0; i < 4; ++i) {
            h[i] = pack_hi(f[2 * i], f[2 * i + 1]);
            l[i] = pack_lo(f[2 * i], f[2 * i + 1]);
        }
        uint32_t ao = ar * 80u + ac * 2u;
        *(uint4*)(p + SA_H + ao) = make_uint4(h[0], h[1], h[2], h[3]);
        *(uint4*)(p + SA_L + ao) = make_uint4(l[0], l[1], l[2], l[3]);
    };

    loadA(0);
    if (t == 0) issueB(0);

    for (int ch = 0; ch < CH / BK; ++ch) {
        mbar_wait(mb_base + (uint32_t)(ch & 1) * 8, (uint32_t)((ch >> 1) & 1));
        storeA(ch);
        __syncthreads();                  // A visible; all warps past compute(ch-1)
        if (ch + 1 < CH / BK) {
            loadA(ch + 1);
            if (t == 0) issueB(ch + 1);
        }

        uint32_t sb = sbase + (uint32_t)(ch & 1) * SBUF;
        #pragma unroll
        for (int ks = 0; ks < BK; ks += 16) {
            uint32_t ah[4][4], al[4][4];
            #pragma unroll
            for (int i = 0; i < 4; ++i) {
                uint32_t mrow = (uint32_t)(wm * 64 + i * 16 + (lane & 15));
                uint32_t kcol = (uint32_t)(ks + (lane >> 4) * 8);
                uint32_t addr = sb + SA_H + mrow * 80u + kcol * 2u;
                LDSM4(ah[i], addr);
                LDSM4(al[i], addr + (SA_L - SA_H));
            }
            #pragma unroll
            for (int p = 0; p < 2; ++p) {
                uint32_t bh[4], bl[4];
                uint32_t krow = (uint32_t)(ks + (lane & 15));
                uint32_t gran = (uint32_t)(wn * 4 + p * 2 + (lane >> 4));
                uint32_t addr = sb + SB_H + krow * 512u + ((gran ^ (krow & 7)) << 4);
                LDSM4T(bh, addr);
                LDSM4T(bl, addr + (SB_L - SB_H));
                #pragma unroll
                for (int i = 0; i < 4; ++i) {
                    MMA(acc[i][2 * p],     ah[i], bh[0], bh[1]);
                    MMA(acc[i][2 * p],     ah[i], bl[0], bl[1]);
                    MMA(acc[i][2 * p],     al[i], bh[0], bh[1]);
                    MMA(acc[i][2 * p + 1], ah[i], bh[2], bh[3]);
                    MMA(acc[i][2 * p + 1], ah[i], bl[2], bl[3]);
                    MMA(acc[i][2 * p + 1], al[i], bh[2], bh[3]);
                }
            }
        }
    }

    // epilogue
    #pragma unroll
    for (int i = 0; i < 4; ++i) {
        int row = m0 + wm * 64 + i * 16 + (lane >> 2);
        float* o0 = out + ((size_t)g * BSZ + row) * CH + wn * 32 + (lane & 3) * 2;
        #pragma unroll
        for (int j = 0; j < 4; ++j) {
            *(float2*)(o0 + j * 8)          = make_float2(acc[i][j][0], acc[i][j][1]);
            *(float2*)(o0 + 8 * CH + j * 8) = make_float2(acc[i][j][2], acc[i][j][3]);
        }
    }
}

// ---------------- entry ----------------------------------------------------
extern "C" void kernel_launch(void* const* d_in, const int* in_sizes, int n_in,
                              void* d_out, int out_size) {
    const float* x = (const float*)d_in[0];
    const float* w = (const float*)d_in[1];
    if (n_in >= 2 && in_sizes[0] < in_sizes[1]) {
        const float* tmp = x; x = w; w = tmp;
    }
    float* out = (float*)d_out;

    cudaFuncSetAttribute(main_mma, cudaFuncAttributeMaxDynamicSharedMemorySize,
                         SMEM_TOTAL);
    cudaFuncSetAttribute(g_mma, cudaFuncAttributeMaxDynamicSharedMemorySize, 65536);
    cudaFuncSetAttribute(q_mma, cudaFuncAttributeMaxDynamicSharedMemorySize, 65536);
    cudaFuncSetAttribute(y_kernel, cudaFuncAttributeMaxDynamicSharedMemorySize,
                         Y_SMEM_BYTES);
    cudaFuncSetAttribute(tinv_kernel, cudaFuncAttributeMaxDynamicSharedMemorySize,
                         TINV_SMEM);

    vsplit<<<GRP * CH * CH / 1024, 256>>>(w);

    dim3 ggrid(3, GRP);
    g_mma<<<ggrid, 256, 65536>>>();

    tinv_kernel<<<GRP, 256, TINV_SMEM>>>();

    dim3 ygrid(CH / 32, GRP);
    y_kernel<<<ygrid, 256, Y_SMEM_BYTES>>>(w);

    dim3 qgrid(4, GRP);
    q_mma<<<qgrid, 256, 65536>>>();

    dim3 mgrid(BSZ / BM, GRP);
    main_mma<<<mgrid, 512, SMEM_TOTAL>>>(x, out);
}

// round 12
// speedup vs baseline: 1.2777x; 1.0611x over previous
#include <cuda_runtime.h>
#include <cuda_bf16.h>
#include <cstdint>

#define GRP 16
#define BSZ 8192
#define CH  256

// ---------------- scratch (device globals; no allocation allowed) ----------
__device__ float g_G[GRP * CH * CH];            // G = V^T V (upper blocks)
__device__ float g_Tinv[GRP * 8 * 32 * 32];     // diag-block inverses of R
__device__ __nv_bfloat16 g_Vhi[GRP * CH * CH];  // W split
__device__ __nv_bfloat16 g_Vlo[GRP * CH * CH];
__device__ __nv_bfloat16 g_Yhi[GRP * CH * CH];  // Y split
__device__ __nv_bfloat16 g_Ylo[GRP * CH * CH];
// Q^T hi/lo as pre-swizzled SMEM images: [GRP][8 chunks][16384 bytes]
__device__ unsigned char g_Qhi_sw[GRP * 8 * 16384];
__device__ unsigned char g_Qlo_sw[GRP * 8 * 16384];

__device__ __forceinline__ uint32_t smem_u32(const void* p) {
    uint32_t a;
    asm("{ .reg .u64 t; cvta.to.shared.u64 t, %1; cvt.u32.u64 %0, t; }"
        : "=r"(a) : "l"(p));
    return a;
}

#define LDSM4(r, addr)                                                      \
    asm volatile("ldmatrix.sync.aligned.m8n8.x4.shared.b16 {%0,%1,%2,%3}, [%4];" \
                 : "=r"((r)[0]), "=r"((r)[1]), "=r"((r)[2]), "=r"((r)[3])   \
                 : "r"(addr))
#define LDSM4T(r, addr)                                                     \
    asm volatile("ldmatrix.sync.aligned.m8n8.x4.trans.shared.b16 {%0,%1,%2,%3}, [%4];" \
                 : "=r"((r)[0]), "=r"((r)[1]), "=r"((r)[2]), "=r"((r)[3])   \
                 : "r"(addr))
#define MMA(c, a, b0, b1)                                                   \
    asm volatile("mma.sync.aligned.m16n8k16.row.col.f32.bf16.bf16.f32 "     \
                 "{%0,%1,%2,%3}, {%4,%5,%6,%7}, {%8,%9}, {%0,%1,%2,%3};"    \
                 : "+f"((c)[0]), "+f"((c)[1]), "+f"((c)[2]), "+f"((c)[3])   \
                 : "r"((a)[0]), "r"((a)[1]), "r"((a)[2]), "r"((a)[3]),      \
                   "r"(b0), "r"(b1))
#define CP16(dst, src)                                                      \
    asm volatile("cp.async.cg.shared.global [%0], [%1], 16;"                \
                 :: "r"(dst), "l"(src) : "memory")

__device__ __forceinline__ void mbar_wait(uint32_t mbar, uint32_t parity) {
    asm volatile(
        "{\n\t.reg .pred P;\n"
        "LW_%=:\n\t"
        "mbarrier.try_wait.parity.acquire.cta.shared::cta.b64 P, [%0], %1, 0x989680;\n\t"
        "@P bra LD_%=;\n\t"
        "bra LW_%=;\n"
        "LD_%=:\n\t}"
        :: "r"(mbar), "r"(parity) : "memory");
}

__device__ __forceinline__ uint32_t pack_hi(float a, float b) {
    __nv_bfloat16 x = __float2bfloat16(a), y = __float2bfloat16(b);
    return ((uint32_t)__bfloat16_as_ushort(y) << 16) | __bfloat16_as_ushort(x);
}
__device__ __forceinline__ uint32_t pack_lo(float a, float b) {
    __nv_bfloat16 x = __float2bfloat16(a), y = __float2bfloat16(b);
    __nv_bfloat16 lx = __float2bfloat16(a - __bfloat162float(x));
    __nv_bfloat16 ly = __float2bfloat16(b - __bfloat162float(y));
    return ((uint32_t)__bfloat16_as_ushort(ly) << 16) | __bfloat16_as_ushort(lx);
}

// ---------------- vsplit: W -> bf16 hi/lo ----------------------------------
__global__ void vsplit(const float* __restrict__ W) {
    int idx = (blockIdx.x * 256 + threadIdx.x) * 4;
    float4 v = *(const float4*)(W + idx);
    uint2 h, l;
    h.x = pack_hi(v.x, v.y); h.y = pack_hi(v.z, v.w);
    l.x = pack_lo(v.x, v.y); l.y = pack_lo(v.z, v.w);
    *(uint2*)&g_Vhi[idx] = h;
    *(uint2*)&g_Vlo[idx] = l;
}

// ---------------- g_mma: G = V^T V (upper 128x128 tiles, HMMA) -------------
#define GSTRIDE 32768u
__global__ void __launch_bounds__(256) g_mma() {
    extern __shared__ __align__(1024) char sm[];
    const uint32_t sb = smem_u32(sm);
    int t = threadIdx.x, warp = t >> 5, lane = t & 31;
    int wm = warp >> 2, wn = warp & 3;
    int g = blockIdx.y;
    int bx = blockIdx.x;                 // 0:(0,0) 1:(0,128) 2:(128,128)
    int a0 = (bx == 2) ? 128 : 0;
    int b0 = (bx == 0) ? 0 : 128;

    const __nv_bfloat16* Vh = g_Vhi + (size_t)g * CH * CH;
    const __nv_bfloat16* Vl = g_Vlo + (size_t)g * CH * CH;

    int kk = t >> 3, g0 = t & 7;
    auto stage = [&](int chk) {
        uint32_t d = sb + (uint32_t)(chk & 1) * GSTRIDE;
        int krow = chk * 32 + kk;
        #pragma unroll
        for (int gi = 0; gi < 2; ++gi) {
            int gr = g0 + gi * 8;
            uint32_t off = (uint32_t)kk * 256 + (uint32_t)((gr ^ (kk & 7)) << 4);
            CP16(d + off,          Vh + (size_t)krow * CH + a0 + gr * 8);
            CP16(d + 8192  + off,  Vl + (size_t)krow * CH + a0 + gr * 8);
            CP16(d + 16384 + off,  Vh + (size_t)krow * CH + b0 + gr * 8);
            CP16(d + 24576 + off,  Vl + (size_t)krow * CH + b0 + gr * 8);
        }
        asm volatile("cp.async.commit_group;" ::: "memory");
    };

    float acc[4][4][4] = {};
    stage(0);
    for (int ch = 0; ch < 8; ++ch) {
        asm volatile("cp.async.wait_group 0;" ::: "memory");
        __syncthreads();
        if (ch < 7) stage(ch + 1);
        uint32_t buf = sb + (uint32_t)(ch & 1) * GSTRIDE;
        #pragma unroll
        for (int ks = 0; ks < 32; ks += 16) {
            uint32_t ah[4][4], al[4][4];
            #pragma unroll
            for (int i = 0; i < 4; ++i) {
                uint32_t mb = (uint32_t)(wm * 64 + i * 16);
                uint32_t krow = (uint32_t)(ks + (lane & 7) + ((lane >> 4) << 3));
                uint32_t gran = (mb >> 3) + ((lane >> 3) & 1);
                uint32_t addr = buf + krow * 256u + ((gran ^ (krow & 7)) << 4);
                LDSM4T(ah[i], addr);
                LDSM4T(al[i], addr + 8192);
            }
            #pragma unroll
            for (int p = 0; p < 2; ++p) {
                uint32_t bh[4], bl[4];
                uint32_t krow = (uint32_t)(ks + (lane & 15));
                uint32_t gran = (uint32_t)(wn * 4 + p * 2 + (lane >> 4));
                uint32_t addr = buf + 16384 + krow * 256u + ((gran ^ (krow & 7)) << 4);
                LDSM4T(bh, addr);
                LDSM4T(bl, addr + 8192);
                #pragma unroll
                for (int i = 0; i < 4; ++i) {
                    MMA(acc[i][2 * p],     ah[i], bh[0], bh[1]);
                    MMA(acc[i][2 * p],     ah[i], bl[0], bl[1]);
                    MMA(acc[i][2 * p],     al[i], bh[0], bh[1]);
                    MMA(acc[i][2 * p + 1], ah[i], bh[2], bh[3]);
                    MMA(acc[i][2 * p + 1], ah[i], bl[2], bl[3]);
                    MMA(acc[i][2 * p + 1], al[i], bh[2], bh[3]);
                }
            }
        }
    }
    float* Gg = g_G + (size_t)g * CH * CH;
    #pragma unroll
    for (int i = 0; i < 4; ++i) {
        int row = a0 + wm * 64 + i * 16 + (lane >> 2);
        #pragma unroll
        for (int j = 0; j < 4; ++j) {
            int col = b0 + wn * 32 + j * 8 + (lane & 3) * 2;
            *(float2*)&Gg[(size_t)row * CH + col]       = make_float2(acc[i][j][0], acc[i][j][1]);
            *(float2*)&Gg[(size_t)(row + 8) * CH + col] = make_float2(acc[i][j][2], acc[i][j][3]);
        }
    }
}

// ---------------- tinv: invert 32x32 diagonal blocks of R (SMEM-staged) ----
#define TINV_SMEM ((8448 + 8448 + 256) * 4)
__global__ void __launch_bounds__(256) tinv_kernel() {
    extern __shared__ __align__(16) float S[];
    float* Gd  = S;            // 8 blocks [32][33]
    float* Ts  = S + 8448;     // 8 blocks [32][33]
    float* bet = S + 16896;

    int g = blockIdx.x;
    int t = threadIdx.x;
    const float* Gg = g_G + (size_t)g * CH * CH;

    for (int e = t; e < 8192; e += 256) {
        int kb = e >> 10, i = (e >> 5) & 31, k = e & 31;
        Gd[kb * 1056 + i * 33 + k] = Gg[(size_t)(kb * 32 + i) * CH + kb * 32 + k];
    }
    bet[t] = 2.0f / Gg[(size_t)t * CH + t];
    __syncthreads();

    int kb = t >> 5, j = t & 31;
    int c0 = kb * 32;
    float* Tb = Ts + kb * 1056;
    const float* Gb = Gd + kb * 1056;
    for (int i = j + 1; i < 32; ++i) Tb[i * 33 + j] = 0.f;
    Tb[j * 33 + j] = bet[c0 + j];
    for (int i = j - 1; i >= 0; --i) {
        float s = 0.f;
        for (int k = i + 1; k <= j; ++k)
            s += Gb[i * 33 + k] * Tb[k * 33 + j];
        Tb[i * 33 + j] = -bet[c0 + i] * s;
    }
    __syncthreads();
    float* Tg = g_Tinv + ((size_t)g * 8 + kb) * 1024;
    for (int i = 0; i < 32; ++i)
        Tg[i * 32 + j] = Tb[i * 33 + j];
}

// ---------------- Y = V R^{-1}: warp-parallel jc accumulation --------------
// smem (floats):
//   GU    @ 0      : 28 blocks [32][32]  (28672)  strict-upper G
//   TD    @ 28672  : 8 blocks  [32][32]  (8192)
//   YS    @ 36864  : [32][264]           (8448)   init = V, becomes Y
//   PRE   @ 45312  : [32][36]            (1152)
//   SPART @ 46464  : 8 x [32][36]        (9216)   per-warp partial sums
#define YGU   0
#define YTD   28672
#define YYS   36864
#define YPRE  45312
#define YSP   46464
#define Y_SMEM_FLOATS 55680
#define Y_SMEM_BYTES  (Y_SMEM_FLOATS * 4)
__global__ void __launch_bounds__(256) y_kernel(const float* __restrict__ W) {
    extern __shared__ __align__(128) float S[];
    const uint32_t sb = smem_u32(S);
    int g  = blockIdx.y;
    int r0 = blockIdx.x * 32;
    int t  = threadIdx.x;

    const float* Vg = W + (size_t)g * CH * CH;
    const float* Gg = g_G + (size_t)g * CH * CH;

    // bulk-load strict-upper G (stride 32), Tinv, and V->Ys via cp.async
    {
        int rr = t >> 3, c = t & 7;
        int p = 0;
        for (int kb = 1; kb < 8; ++kb)
            for (int jc = 0; jc < kb; ++jc, ++p)
                CP16(sb + (uint32_t)(YGU + p * 1024 + rr * 32 + c * 4) * 4,
                     Gg + (size_t)(jc * 32 + rr) * CH + kb * 32 + c * 4);
        const float* Tg = g_Tinv + (size_t)g * 8 * 1024;
        for (int kb = 0; kb < 8; ++kb)
            CP16(sb + (uint32_t)(YTD + kb * 1024 + rr * 32 + c * 4) * 4,
                 Tg + (size_t)kb * 1024 + rr * 32 + c * 4);
        for (int cc = c; cc < 64; cc += 8)
            CP16(sb + (uint32_t)(YYS + rr * 264 + cc * 4) * 4,
                 Vg + (size_t)(r0 + rr) * CH + cc * 4);
        asm volatile("cp.async.commit_group;" ::: "memory");
        asm volatile("cp.async.wait_group 0;" ::: "memory");
    }
    __syncthreads();

    int w = t >> 5, l = t & 31;
    int q = l & 7, r2 = l >> 3;        // accumulation: 8 rows per thread
    int r = t >> 3, q8 = t & 7;        // reduction/Td: 1 row, 4 cols per thread

    for (int kb = 0; kb < 8; ++kb) {
        int c0 = kb * 32;
        // --- warp-parallel partial accumulation over jc blocks
        float a[8][4] = {};
        int pbase = kb * (kb - 1) / 2;
        for (int jc = w; jc < kb; jc += 8) {
            const float* Gb = S + YGU + (pbase + jc) * 1024 + 4 * q;
            int j0 = jc * 32;
            #pragma unroll
            for (int jj = 0; jj < 32; ++jj) {
                float4 gg = *(const float4*)(Gb + jj * 32);
                #pragma unroll
                for (int ri = 0; ri < 8; ++ri) {
                    float yv = S[YYS + (r2 + 4 * ri) * 264 + j0 + jj];
                    a[ri][0] += yv * gg.x;
                    a[ri][1] += yv * gg.y;
                    a[ri][2] += yv * gg.z;
                    a[ri][3] += yv * gg.w;
                }
            }
        }
        #pragma unroll
        for (int ri = 0; ri < 8; ++ri) {
            float4 v = {a[ri][0], a[ri][1], a[ri][2], a[ri][3]};
            *(float4*)(S + YSP + w * 1152 + (r2 + 4 * ri) * 36 + 4 * q) = v;
        }
        __syncthreads();
        // --- reduce partials; pre = V - sum  (Ys cols c0 still hold V)
        float4 pr = *(const float4*)(S + YYS + r * 264 + c0 + 4 * q8);
        #pragma unroll
        for (int w2 = 0; w2 < 8; ++w2) {
            float4 s = *(const float4*)(S + YSP + w2 * 1152 + r * 36 + 4 * q8);
            pr.x -= s.x; pr.y -= s.y; pr.z -= s.z; pr.w -= s.w;
        }
        *(float4*)(S + YPRE + r * 36 + 4 * q8) = pr;
        __syncwarp();
        // --- Y block = pre @ Td  (row-local within warp)
        const float* Tdb = S + YTD + kb * 1024 + 4 * q8;
        float o0 = 0.f, o1 = 0.f, o2 = 0.f, o3 = 0.f;
        #pragma unroll
        for (int i = 0; i < 32; ++i) {
            float pv = S[YPRE + r * 36 + i];
            float4 tv = *(const float4*)(Tdb + i * 32);
            o0 += pv * tv.x;
            o1 += pv * tv.y;
            o2 += pv * tv.z;
            o3 += pv * tv.w;
        }
        float4 ov = {o0, o1, o2, o3};
        *(float4*)(S + YYS + r * 264 + c0 + 4 * q8) = ov;
        __syncthreads();
    }

    for (int e = t; e < 32 * (CH / 2); e += 256) {
        int rr = e >> 7, cc = (e & 127) * 2;
        float v0 = S[YYS + rr * 264 + cc], v1 = S[YYS + rr * 264 + cc + 1];
        size_t idx = ((size_t)g * CH + r0 + rr) * CH + cc;
        *(uint32_t*)&g_Yhi[idx] = pack_hi(v0, v1);
        *(uint32_t*)&g_Ylo[idx] = pack_lo(v0, v1);
    }
}

// ---------------- q_mma: Q = I - Y V^T, emits pre-swizzled Q images --------
#define QSTRIDE 32768u
__global__ void __launch_bounds__(256) q_mma() {
    extern __shared__ __align__(1024) char sm[];
    const uint32_t sb = smem_u32(sm);
    int t = threadIdx.x, warp = t >> 5, lane = t & 31;
    int wm = warp >> 2, wn = warp & 3;
    int g = blockIdx.y;
    int a0 = (blockIdx.x >> 1) * 128, b0 = (blockIdx.x & 1) * 128;

    const __nv_bfloat16* Yh = g_Yhi + (size_t)g * CH * CH;
    const __nv_bfloat16* Yl = g_Ylo + (size_t)g * CH * CH;
    const __nv_bfloat16* Vh = g_Vhi + (size_t)g * CH * CH;
    const __nv_bfloat16* Vl = g_Vlo + (size_t)g * CH * CH;

    int row = t >> 1, gp = (t & 1) * 2;
    auto stage = [&](int chk) {
        uint32_t d = sb + (uint32_t)(chk & 1) * QSTRIDE;
        int k0 = chk * 32;
        #pragma unroll
        for (int gi = 0; gi < 2; ++gi) {
            int gr = gp + gi;
            uint32_t off = (uint32_t)row * 64 + (uint32_t)((gr ^ ((row >> 1) & 3)) << 4);
            CP16(d + off,          Yh + (size_t)(a0 + row) * CH + k0 + gr * 8);
            CP16(d + 8192  + off,  Yl + (size_t)(a0 + row) * CH + k0 + gr * 8);
            CP16(d + 16384 + off,  Vh + (size_t)(b0 + row) * CH + k0 + gr * 8);
            CP16(d + 24576 + off,  Vl + (size_t)(b0 + row) * CH + k0 + gr * 8);
        }
        asm volatile("cp.async.commit_group;" ::: "memory");
    };

    float acc[4][4][4] = {};
    stage(0);
    for (int ch = 0; ch < 8; ++ch) {
        asm volatile("cp.async.wait_group 0;" ::: "memory");
        __syncthreads();
        if (ch < 7) stage(ch + 1);
        uint32_t buf = sb + (uint32_t)(ch & 1) * QSTRIDE;
        #pragma unroll
        for (int ks = 0; ks < 32; ks += 16) {
            uint32_t ah[4][4], al[4][4];
            #pragma unroll
            for (int i = 0; i < 4; ++i) {
                uint32_t mrow = (uint32_t)(wm * 64 + i * 16 + (lane & 15));
                uint32_t gran = (uint32_t)((ks >> 3) + (lane >> 4));
                uint32_t addr = buf + mrow * 64u + ((gran ^ ((mrow >> 1) & 3)) << 4);
                LDSM4(ah[i], addr);
                LDSM4(al[i], addr + 8192);
            }
            #pragma unroll
            for (int p = 0; p < 2; ++p) {
                uint32_t bh[4], bl[4];
                uint32_t nrow = (uint32_t)(wn * 32 + p * 16 + (lane & 7) + ((lane >> 4) << 3));
                uint32_t gran = (uint32_t)((ks >> 3) + ((lane >> 3) & 1));
                uint32_t addr = buf + 16384 + nrow * 64u + ((gran ^ ((nrow >> 1) & 3)) << 4);
                LDSM4(bh, addr);
                LDSM4(bl, addr + 8192);
                #pragma unroll
                for (int i = 0; i < 4; ++i) {
                    MMA(acc[i][2 * p],     ah[i], bh[0], bh[1]);
                    MMA(acc[i][2 * p],     ah[i], bl[0], bl[1]);
                    MMA(acc[i][2 * p],     al[i], bh[0], bh[1]);
                    MMA(acc[i][2 * p + 1], ah[i], bh[2], bh[3]);
                    MMA(acc[i][2 * p + 1], ah[i], bl[2], bl[3]);
                    MMA(acc[i][2 * p + 1], al[i], bh[2], bh[3]);
                }
            }
        }
    }
    // epilogue: write swizzled global images
    unsigned char* QH = g_Qhi_sw + (size_t)g * 8 * 16384;
    unsigned char* QL = g_Qlo_sw + (size_t)g * 8 * 16384;
    #pragma unroll
    for (int i = 0; i < 4; ++i) {
        int rr = a0 + wm * 64 + i * 16 + (lane >> 2);
        #pragma unroll
        for (int j = 0; j < 4; ++j) {
            int cc = b0 + wn * 32 + j * 8 + (lane & 3) * 2;
            float v0 = (rr == cc     ? 1.f : 0.f) - acc[i][j][0];
            float v1 = (rr == cc + 1 ? 1.f : 0.f) - acc[i][j][1];
            float v2 = (rr + 8 == cc     ? 1.f : 0.f) - acc[i][j][2];
            float v3 = (rr + 8 == cc + 1 ? 1.f : 0.f) - acc[i][j][3];
            int gran = cc >> 3, sub = (cc & 7) * 2;
            #pragma unroll
            for (int rh = 0; rh < 2; ++rh) {
                int k = rr + rh * 8;
                int chunk = k >> 5, krw = k & 31;
                size_t off = (size_t)chunk * 16384 + krw * 512 +
                             ((gran ^ (krw & 7)) << 4) + sub;
                *(uint32_t*)(QH + off) = pack_hi(rh ? v2 : v0, rh ? v3 : v1);
                *(uint32_t*)(QL + off) = pack_lo(rh ? v2 : v0, rh ? v3 : v1);
            }
        }
    }
}

// ---------------- out = x @ Q: mma.sync + 3-deep bulk B pipeline -----------
#define BM 128
#define BN 256
#define BK 32
#define ABUF 20480u          // per A buffer: hi 10240 + lo 10240
#define BBASE 40960u
#define BBUF 32768u          // per B buffer: hi 16384 + lo 16384
#define SMEM_TOTAL (BBASE + 3u * BBUF)   // 139264

__global__ void __launch_bounds__(512, 1) main_mma(const float* __restrict__ X,
                                                   float* __restrict__ out) {
    extern __shared__ __align__(1024) char sm[];
    __shared__ __align__(8) uint64_t mbars[3];
    const uint32_t sbase = smem_u32(sm);
    const uint32_t mb_base = smem_u32(mbars);

    int t = threadIdx.x;
    int warp = t >> 5, lane = t & 31;
    int wm = warp >> 3, wn = warp & 7;      // warp tile 64m x 32n
    int g = blockIdx.y;
    int m0 = blockIdx.x * BM;

    const float* Xg = X + ((size_t)g * BSZ + m0) * CH;
    const unsigned char* QH = g_Qhi_sw + (size_t)g * 8 * 16384;
    const unsigned char* QL = g_Qlo_sw + (size_t)g * 8 * 16384;

    if (t == 0) {
        asm volatile("mbarrier.init.shared.b64 [%0], 1;" :: "r"(mb_base) : "memory");
        asm volatile("mbarrier.init.shared.b64 [%0], 1;" :: "r"(mb_base + 8) : "memory");
        asm volatile("mbarrier.init.shared.b64 [%0], 1;" :: "r"(mb_base + 16) : "memory");
    }
    __syncthreads();

    int ar = t >> 2, ac = (t & 3) * 8;

    float acc[4][4][4] = {};
    float4 xa[2];

    auto loadA = [&](int ch) {
        xa[0] = *(const float4*)(Xg + (size_t)ar * CH + ch * BK + ac);
        xa[1] = *(const float4*)(Xg + (size_t)ar * CH + ch * BK + ac + 4);
    };
    auto issueB = [&](int ch) {   // call with t == 0 only
        int b = ch % 3;
        uint32_t mbar = mb_base + (uint32_t)b * 8;
        uint32_t dH = sbase + BBASE + (uint32_t)b * BBUF;
        uint32_t dL = dH + 16384u;
        const unsigned char* sH = QH + (size_t)ch * 16384;
        const unsigned char* sL = QL + (size_t)ch * 16384;
        asm volatile("mbarrier.arrive.expect_tx.shared.b64 _, [%0], %1;"
                     :: "r"(mbar), "r"(32768u) : "memory");
        asm volatile("cp.async.bulk.shared::cluster.global.mbarrier::complete_tx::bytes "
                     "[%0], [%1], %2, [%3];"
                     :: "r"(dH), "l"(sH), "r"(16384u), "r"(mbar) : "memory");
        asm volatile("cp.async.bulk.shared::cluster.global.mbarrier::complete_tx::bytes "
                     "[%0], [%1], %2, [%3];"
                     :: "r"(dL), "l"(sL), "r"(16384u), "r"(mbar) : "memory");
    };
    auto storeA = [&](int ch) {
        char* p = sm + (ch & 1) * ABUF;
        float f[8] = {xa[0].x, xa[0].y, xa[0].z, xa[0].w,
                      xa[1].x, xa[1].y, xa[1].z, xa[1].w};
        uint32_t h[4], l[4];
        #pragma unroll
        for (int i = 0; i < 4; ++i) {
            h[i] = pack_hi(f[2 * i], f[2 * i + 1]);
            l[i] = pack_lo(f[2 * i], f[2 * i + 1]);
        }
        uint32_t ao = ar * 80u + ac * 2u;
        *(uint4*)(p + ao)         = make_uint4(h[0], h[1], h[2], h[3]);
        *(uint4*)(p + 10240 + ao) = make_uint4(l[0], l[1], l[2], l[3]);
    };

    loadA(0);
    if (t == 0) { issueB(0); issueB(1); }

    for (int ch = 0; ch < CH / BK; ++ch) {
        mbar_wait(mb_base + (uint32_t)(ch % 3) * 8, (uint32_t)((ch / 3) & 1));
        storeA(ch);
        __syncthreads();   // all warps past compute(ch-1); A(ch) visible
        if (t == 0 && ch + 2 < CH / BK) issueB(ch + 2);   // buffer (ch-1)%3 now free
        if (ch + 1 < CH / BK) loadA(ch + 1);

        uint32_t abuf = sbase + (uint32_t)(ch & 1) * ABUF;
        uint32_t bbuf = sbase + BBASE + (uint32_t)(ch % 3) * BBUF;
        #pragma unroll
        for (int ks = 0; ks < BK; ks += 16) {
            uint32_t ah[4][4], al[4][4];
            #pragma unroll
            for (int i = 0; i < 4; ++i) {
                uint32_t mrow = (uint32_t)(wm * 64 + i * 16 + (lane & 15));
                uint32_t kcol = (uint32_t)(ks + (lane >> 4) * 8);
                uint32_t addr = abuf + mrow * 80u + kcol * 2u;
                LDSM4(ah[i], addr);
                LDSM4(al[i], addr + 10240u);
            }
            #pragma unroll
            for (int p = 0; p < 2; ++p) {
                uint32_t bh[4], bl[4];
                uint32_t krow = (uint32_t)(ks + (lane & 15));
                uint32_t gran = (uint32_t)(wn * 4 + p * 2 + (lane >> 4));
                uint32_t addr = bbuf + krow * 512u + ((gran ^ (krow & 7)) << 4);
                LDSM4T(bh, addr);
                LDSM4T(bl, addr + 16384u);
                #pragma unroll
                for (int i = 0; i < 4; ++i) {
                    MMA(acc[i][2 * p],     ah[i], bh[0], bh[1]);
                    MMA(acc[i][2 * p],     ah[i], bl[0], bl[1]);
                    MMA(acc[i][2 * p],     al[i], bh[0], bh[1]);
                    MMA(acc[i][2 * p + 1], ah[i], bh[2], bh[3]);
                    MMA(acc[i][2 * p + 1], ah[i], bl[2], bl[3]);
                    MMA(acc[i][2 * p + 1], al[i], bh[2], bh[3]);
                }
            }
        }
    }

    // epilogue
    #pragma unroll
    for (int i = 0; i < 4; ++i) {
        int row = m0 + wm * 64 + i * 16 + (lane >> 2);
        float* o0 = out + ((size_t)g * BSZ + row) * CH + wn * 32 + (lane & 3) * 2;
        #pragma unroll
        for (int j = 0; j < 4; ++j) {
            *(float2*)(o0 + j * 8)          = make_float2(acc[i][j][0], acc[i][j][1]);
            *(float2*)(o0 + 8 * CH + j * 8) = make_float2(acc[i][j][2], acc[i][j][3]);
        }
    }
}

// ---------------- entry ----------------------------------------------------
extern "C" void kernel_launch(void* const* d_in, const int* in_sizes, int n_in,
                              void* d_out, int out_size) {
    const float* x = (const float*)d_in[0];
    const float* w = (const float*)d_in[1];
    if (n_in >= 2 && in_sizes[0] < in_sizes[1]) {
        const float* tmp = x; x = w; w = tmp;
    }
    float* out = (float*)d_out;

    cudaFuncSetAttribute(main_mma, cudaFuncAttributeMaxDynamicSharedMemorySize,
                         SMEM_TOTAL);
    cudaFuncSetAttribute(g_mma, cudaFuncAttributeMaxDynamicSharedMemorySize, 65536);
    cudaFuncSetAttribute(q_mma, cudaFuncAttributeMaxDynamicSharedMemorySize, 65536);
    cudaFuncSetAttribute(y_kernel, cudaFuncAttributeMaxDynamicSharedMemorySize,
                         Y_SMEM_BYTES);
    cudaFuncSetAttribute(tinv_kernel, cudaFuncAttributeMaxDynamicSharedMemorySize,
                         TINV_SMEM);

    vsplit<<<GRP * CH * CH / 1024, 256>>>(w);

    dim3 ggrid(3, GRP);
    g_mma<<<ggrid, 256, 65536>>>();

    tinv_kernel<<<GRP, 256, TINV_SMEM>>>();

    dim3 ygrid(CH / 32, GRP);
    y_kernel<<<ygrid, 256, Y_SMEM_BYTES>>>(w);

    dim3 qgrid(4, GRP);
    q_mma<<<qgrid, 256, 65536>>>();

    dim3 mgrid(BSZ / BM, GRP);
    main_mma<<<mgrid, 512, SMEM_TOTAL>>>(x, out);
}